// round 5
// baseline (speedup 1.0000x reference)
#include <cuda_runtime.h>
#include <math.h>

#define VSZ 32000
#define ESZ 400
#define HSZ 1150
#define HPAD 1152
#define BSZ 16
#define TSZ 128
#define GP12 4608   // padded gate-col count for layers 1/2 (144 CTAs * 32)
#define GP3  1600   // layer 3 gate cols (50 CTAs * 32)

// ---------------- scratch (device globals; no allocation allowed) ----------------
__device__ float g_y0[TSZ*BSZ*ESZ];
__device__ float g_y1[TSZ*BSZ*HPAD];
__device__ float g_y2[TSZ*BSZ*HPAD];
__device__ float g_y3[TSZ*BSZ*ESZ];
__device__ float g_pre[TSZ*BSZ*4*HSZ];
__device__ float g_Wt1[HSZ*GP12];
__device__ float g_Wt2[HSZ*GP12];
__device__ float g_Wt3[ESZ*GP3];
__device__ float g_Wih2p[4*HSZ*HPAD];
__device__ float g_Wih3p[4*ESZ*HPAD];
__device__ float g_hTa[HSZ*BSZ];
__device__ float g_hTb[HSZ*BSZ];
__device__ float g_cT1[HSZ*BSZ];
__device__ float g_cT2[HSZ*BSZ];
__device__ float g_cT3[ESZ*BSZ];
__device__ unsigned g_bar[4];

// ---------------- tiny utility kernels ----------------
__global__ void zero_k(float* __restrict__ p, int n) {
    int i = blockIdx.x * blockDim.x + threadIdx.x;
    if (i < n) p[i] = 0.f;
}

__global__ void pad_k(const float* __restrict__ src, float* __restrict__ dst,
                      int rows, int Kin, int Kout) {
    int idx = blockIdx.x * blockDim.x + threadIdx.x;
    if (idx >= rows * Kout) return;
    int r = idx / Kout, k = idx % Kout;
    dst[idx] = (k < Kin) ? src[(size_t)r * Kin + k] : 0.f;
}

__global__ void embed_k(const float* __restrict__ emb, const int* __restrict__ x,
                        float* __restrict__ y0) {
    int idx = blockIdx.x * blockDim.x + threadIdx.x;
    if (idx >= TSZ * BSZ * ESZ) return;
    int e   = idx % ESZ;
    int row = idx / ESZ;      // b*T + t
    y0[idx] = emb[(size_t)x[row] * ESZ + e];
}

// Gate-permuted transpose of W_hh
__global__ void wtrans_k(const float* __restrict__ W, float* __restrict__ Wt,
                         int Hp, int Gp) {
    __shared__ float tile[32][33];
    int jblk = blockIdx.x;
    int k0   = blockIdx.y * 32;
    for (int rr = 0; rr < 32; rr += 8) {
        int r = rr + threadIdx.y;
        int g = r >> 3, u = r & 7;
        int j = jblk * 8 + u;
        int orow = g * Hp + j;
        int k = k0 + threadIdx.x;
        tile[r][threadIdx.x] = (j < Hp && k < Hp) ? W[(size_t)orow * Hp + k] : 0.f;
    }
    __syncthreads();
    for (int kk = 0; kk < 32; kk += 8) {
        int k = k0 + kk + threadIdx.y;
        if (k < Hp)
            Wt[(size_t)k * Gp + jblk * 32 + threadIdx.x] = tile[threadIdx.x][kk + threadIdx.y];
    }
}

// ---------------- tf32x2 tensor-core GEMM ----------------
__device__ __forceinline__ float tf32_rna(float x) {
    float r;
    asm("cvt.rna.tf32.f32 %0, %1;" : "=f"(r) : "f"(x));
    return r;
}

__device__ __forceinline__ void mma_tf32(float4& d, const float* a, const float* b) {
    asm volatile(
        "mma.sync.aligned.m16n8k8.row.col.f32.tf32.tf32.f32 "
        "{%0,%1,%2,%3}, {%4,%5,%6,%7}, {%8,%9}, {%0,%1,%2,%3};\n"
        : "+f"(d.x), "+f"(d.y), "+f"(d.z), "+f"(d.w)
        : "r"(__float_as_uint(a[0])), "r"(__float_as_uint(a[1])),
          "r"(__float_as_uint(a[2])), "r"(__float_as_uint(a[3])),
          "r"(__float_as_uint(b[0])), "r"(__float_as_uint(b[1])));
}

#define SSTR 20

__global__ __launch_bounds__(256)
void gemm_tc(const float* __restrict__ A, const float* __restrict__ Bm,
             const float* __restrict__ bias1, const float* __restrict__ bias2,
             float* __restrict__ C, int M, int N, int K, int mode) {
    __shared__ float As[2][128 * SSTR];
    __shared__ float Bs[2][128 * SSTR];

    const int tid  = threadIdx.x;
    const int lane = tid & 31;
    const int w    = tid >> 5;
    const int wm   = (w & 1) * 64;
    const int wn   = (w >> 1) * 32;
    const int qr   = lane >> 2;
    const int qc   = lane & 3;

    const int m0 = blockIdx.y * 128;
    const int n0 = blockIdx.x * 128;

    const int lrow = tid >> 1;
    const int lk   = (tid & 1) * 8;

    const float* Aptr = A + (size_t)(m0 + lrow) * K + lk;
    const float* Bptr = Bm + (size_t)(n0 + lrow) * K + lk;
    const bool bvalid = (n0 + lrow) < N;

    float4 acc[4][4];
#pragma unroll
    for (int i = 0; i < 4; i++)
#pragma unroll
        for (int j = 0; j < 4; j++) acc[i][j] = make_float4(0.f, 0.f, 0.f, 0.f);

    for (int k0 = 0; k0 < K; k0 += 16) {
        float4 av0 = *(const float4*)(Aptr + k0);
        float4 av1 = *(const float4*)(Aptr + k0 + 4);
        float4 bv0 = bvalid ? *(const float4*)(Bptr + k0) : make_float4(0.f, 0.f, 0.f, 0.f);
        float4 bv1 = bvalid ? *(const float4*)(Bptr + k0 + 4) : make_float4(0.f, 0.f, 0.f, 0.f);
        __syncthreads();
        {
            float va[8] = {av0.x, av0.y, av0.z, av0.w, av1.x, av1.y, av1.z, av1.w};
            float vb[8] = {bv0.x, bv0.y, bv0.z, bv0.w, bv1.x, bv1.y, bv1.z, bv1.w};
            int base = lrow * SSTR + lk;
#pragma unroll
            for (int j = 0; j < 8; j++) {
                float hi = tf32_rna(va[j]);
                As[0][base + j] = hi;
                As[1][base + j] = tf32_rna(va[j] - hi);
                float bhi = tf32_rna(vb[j]);
                Bs[0][base + j] = bhi;
                Bs[1][base + j] = tf32_rna(vb[j] - bhi);
            }
        }
        __syncthreads();

#pragma unroll
        for (int kk = 0; kk < 16; kk += 8) {
            float ah[4][4], al[4][4], bh[4][2], bl[4][2];
#pragma unroll
            for (int mt = 0; mt < 4; mt++) {
                int base = (wm + mt * 16 + qr) * SSTR + kk + qc;
                ah[mt][0] = As[0][base];
                ah[mt][1] = As[0][base + 8 * SSTR];
                ah[mt][2] = As[0][base + 4];
                ah[mt][3] = As[0][base + 8 * SSTR + 4];
                al[mt][0] = As[1][base];
                al[mt][1] = As[1][base + 8 * SSTR];
                al[mt][2] = As[1][base + 4];
                al[mt][3] = As[1][base + 8 * SSTR + 4];
            }
#pragma unroll
            for (int nt = 0; nt < 4; nt++) {
                int base = (wn + nt * 8 + qr) * SSTR + kk + qc;
                bh[nt][0] = Bs[0][base];
                bh[nt][1] = Bs[0][base + 4];
                bl[nt][0] = Bs[1][base];
                bl[nt][1] = Bs[1][base + 4];
            }
#pragma unroll
            for (int mt = 0; mt < 4; mt++)
#pragma unroll
                for (int nt = 0; nt < 4; nt++) {
                    mma_tf32(acc[mt][nt], ah[mt], bh[nt]);
                    mma_tf32(acc[mt][nt], ah[mt], bl[nt]);
                    mma_tf32(acc[mt][nt], al[mt], bh[nt]);
                }
        }
    }

#pragma unroll
    for (int mt = 0; mt < 4; mt++) {
        int mrow = m0 + wm + mt * 16 + qr;
#pragma unroll
        for (int nt = 0; nt < 4; nt++) {
            int n = n0 + wn + nt * 8 + 2 * qc;
            if (n >= N) continue;
            float b0 = 0.f, b1 = 0.f;
            if (bias1) { b0 += bias1[n]; b1 += bias1[n + 1]; }
            if (bias2) { b0 += bias2[n]; b1 += bias2[n + 1]; }
            float4 v = acc[mt][nt];
            if (mode == 0) {
                C[(size_t)mrow * N + n]           = v.x + b0;
                C[(size_t)mrow * N + n + 1]       = v.y + b1;
                C[(size_t)(mrow + 8) * N + n]     = v.z + b0;
                C[(size_t)(mrow + 8) * N + n + 1] = v.w + b1;
            } else {
                int bidx = m0 >> 7;
                int t = (mrow - m0);
                size_t base = ((size_t)bidx * N + n) * TSZ + t;
                C[base]           = v.x + b0;
                C[base + TSZ]     = v.y + b1;
                C[base + 8]       = v.z + b0;
                C[base + TSZ + 8] = v.w + b1;
            }
        }
    }
}

// ---------------- persistent LSTM layer kernel (f32x2 inner loop) ----------------
__device__ __forceinline__ float sigf(float z) { return 1.f / (1.f + expf(-z)); }

#define FMA2(d, a, b) \
    asm("fma.rn.f32x2 %0, %1, %2, %0;" : "+l"(d) : "l"(a), "l"(b))

__device__ __forceinline__ void grid_bar(unsigned* bar, unsigned target) {
    __syncthreads();
    if (threadIdx.x == 0) {
        __threadfence();
        atomicAdd(bar, 1u);
        while (*(volatile unsigned*)bar < target) __nanosleep(64);
        __threadfence();
    }
    __syncthreads();
}

__global__ __launch_bounds__(256, 1)
void lstm_layer_k(const float* __restrict__ pre, const float* __restrict__ Wt,
                  float* __restrict__ hA, float* __restrict__ hB,
                  float* __restrict__ cOut, float* __restrict__ y,
                  int Hp, int Gp, int ldy, unsigned* bar) {
    extern __shared__ float sm[];
    float* sW  = sm;                 // Hp*32
    float* red = sm + Hp * 32;       // 8*32*16 = 4096
    float* cT  = red + 4096;         // 128

    const int tid  = threadIdx.x;
    const int jblk = blockIdx.x;
    const int nCTA = gridDim.x;
    const int r = tid & 31;
    const int s = tid >> 5;
    const int G4 = 4 * Hp;

    // epilogue thread mapping (computed once)
    const int eu = tid >> 4;            // unit within block (tid<128)
    const int eb = tid & 15;            // batch
    const int ej = jblk * 8 + eu;
    const bool eact = (tid < 128) && (ej < Hp);
    const bool epad = (tid < 128) && (ej >= Hp) && (ej < ldy);  // zero-fill pad cols

    // stage weights into smem (coalesced)
    for (int idx = tid; idx < Hp * 32; idx += 256) {
        int k = idx >> 5, rr = idx & 31;
        sW[idx] = Wt[(size_t)k * Gp + jblk * 32 + rr];
    }
    if (tid < 128) {
        cT[tid] = 0.f;
        if (ej < Hp) hA[ej * 16 + eb] = 0.f;
    }
    grid_bar(bar, (unsigned)nCTA);

    for (int t = 0; t < TSZ; t++) {
        const float* hin = (t & 1) ? hB : hA;
        float* hout      = (t & 1) ? hA : hB;

        // prefetch pre-activation gate values early (independent of h)
        float pg[4];
        size_t erow = (size_t)eb * TSZ + t;
        if (eact) {
            const float* prow = pre + erow * G4 + ej;
#pragma unroll
            for (int g = 0; g < 4; g++) pg[g] = __ldcg(prow + (size_t)g * Hp);
        }

        unsigned long long acc2[8];
#pragma unroll
        for (int i = 0; i < 8; i++) acc2[i] = 0ULL;

        const ulonglong2* hv = (const ulonglong2*)hin;  // h[k*16+b], 4 pairs per 16B
#pragma unroll 4
        for (int k = s; k < Hp; k += 8) {
            float wf = sW[(k << 5) + r];
            unsigned wu = __float_as_uint(wf);
            unsigned long long w2;
            asm("mov.b64 %0, {%1, %1};" : "=l"(w2) : "r"(wu));
            ulonglong2 p0 = hv[k * 4 + 0];
            ulonglong2 p1 = hv[k * 4 + 1];
            ulonglong2 p2 = hv[k * 4 + 2];
            ulonglong2 p3 = hv[k * 4 + 3];
            FMA2(acc2[0], w2, p0.x); FMA2(acc2[1], w2, p0.y);
            FMA2(acc2[2], w2, p1.x); FMA2(acc2[3], w2, p1.y);
            FMA2(acc2[4], w2, p2.x); FMA2(acc2[5], w2, p2.y);
            FMA2(acc2[6], w2, p3.x); FMA2(acc2[7], w2, p3.y);
        }

        ulonglong2* rp = (ulonglong2*)&red[(s * 32 + r) * 16];
        rp[0] = make_ulonglong2(acc2[0], acc2[1]);
        rp[1] = make_ulonglong2(acc2[2], acc2[3]);
        rp[2] = make_ulonglong2(acc2[4], acc2[5]);
        rp[3] = make_ulonglong2(acc2[6], acc2[7]);
        __syncthreads();

        if (eact) {
            float gv[4];
#pragma unroll
            for (int g = 0; g < 4; g++) {
                float sum = pg[g];
#pragma unroll
                for (int s2 = 0; s2 < 8; s2++)
                    sum += red[(s2 * 32 + g * 8 + eu) * 16 + eb];
                gv[g] = sum;
            }
            float ig = sigf(gv[0]);
            float fg = sigf(gv[1]);
            float gg = tanhf(gv[2]);
            float og = sigf(gv[3]);
            float c  = fg * cT[tid] + ig * gg;
            float hn = og * tanhf(c);
            cT[tid] = c;
            hout[ej * 16 + eb] = hn;
            y[erow * ldy + ej] = hn;
            if (t == TSZ - 1) cOut[ej * 16 + eb] = c;
        } else if (epad) {
            y[erow * ldy + ej] = 0.f;   // zero the K-padding columns for next GEMM
        }
        grid_bar(bar, (unsigned)(nCTA * (t + 2)));
    }
}

// ---------------- finalize ----------------
__global__ void finalize_k(const float* __restrict__ y1, const float* __restrict__ y2,
                           const float* __restrict__ y3, const float* __restrict__ cT1,
                           const float* __restrict__ cT2, const float* __restrict__ cT3,
                           float* __restrict__ out) {
    int i = blockIdx.x * blockDim.x + threadIdx.x;
    if (i >= 86400) return;
    const size_t O = (size_t)BSZ * VSZ * TSZ;
    if (i < 18400) {
        int b = i / 1150, j = i % 1150;
        out[O + i] = y1[((size_t)b * TSZ + 127) * HPAD + j];
    } else if (i < 36800) {
        int k = i - 18400; int b = k / 1150, j = k % 1150;
        out[O + i] = y2[((size_t)b * TSZ + 127) * HPAD + j];
    } else if (i < 43200) {
        int k = i - 36800; int b = k / 400, j = k % 400;
        out[O + i] = y3[((size_t)b * TSZ + 127) * 400 + j];
    } else if (i < 61600) {
        int k = i - 43200; int j = (k % 1150), b = k / 1150;
        out[O + i] = cT1[j * 16 + b];
    } else if (i < 80000) {
        int k = i - 61600; int j = (k % 1150), b = k / 1150;
        out[O + i] = cT2[j * 16 + b];
    } else {
        int k = i - 80000; int j = (k % 400), b = k / 400;
        out[O + i] = cT3[j * 16 + b];
    }
}

// ---------------- launch ----------------
extern "C" void kernel_launch(void* const* d_in, const int* in_sizes, int n_in,
                              void* d_out, int out_size) {
    const float* emb  = (const float*)d_in[0];
    const float* Wih1 = (const float*)d_in[1];
    const float* Whh1 = (const float*)d_in[2];
    const float* bih1 = (const float*)d_in[3];
    const float* bhh1 = (const float*)d_in[4];
    const float* Wih2 = (const float*)d_in[5];
    const float* Whh2 = (const float*)d_in[6];
    const float* bih2 = (const float*)d_in[7];
    const float* bhh2 = (const float*)d_in[8];
    const float* Wih3 = (const float*)d_in[9];
    const float* Whh3 = (const float*)d_in[10];
    const float* bih3 = (const float*)d_in[11];
    const float* bhh3 = (const float*)d_in[12];
    const float* linb = (const float*)d_in[13];
    const int*   x    = (const int*)d_in[14];
    float* out = (float*)d_out;

    float *y0, *y1, *y2, *y3, *pre, *Wt1, *Wt2, *Wt3, *W2p, *W3p;
    float *hTa, *hTb, *cT1, *cT2, *cT3;
    unsigned* bar;
    cudaGetSymbolAddress((void**)&y0,  g_y0);
    cudaGetSymbolAddress((void**)&y1,  g_y1);
    cudaGetSymbolAddress((void**)&y2,  g_y2);
    cudaGetSymbolAddress((void**)&y3,  g_y3);
    cudaGetSymbolAddress((void**)&pre, g_pre);
    cudaGetSymbolAddress((void**)&Wt1, g_Wt1);
    cudaGetSymbolAddress((void**)&Wt2, g_Wt2);
    cudaGetSymbolAddress((void**)&Wt3, g_Wt3);
    cudaGetSymbolAddress((void**)&W2p, g_Wih2p);
    cudaGetSymbolAddress((void**)&W3p, g_Wih3p);
    cudaGetSymbolAddress((void**)&hTa, g_hTa);
    cudaGetSymbolAddress((void**)&hTb, g_hTb);
    cudaGetSymbolAddress((void**)&cT1, g_cT1);
    cudaGetSymbolAddress((void**)&cT2, g_cT2);
    cudaGetSymbolAddress((void**)&cT3, g_cT3);
    cudaGetSymbolAddress((void**)&bar, g_bar);

    const int M = TSZ * BSZ;  // 2048
    const int SMEM12 = (HSZ * 32 + 4096 + 128) * 4;  // 164096 B
    const int SMEM3  = (ESZ * 32 + 4096 + 128) * 4;  //  68096 B
    static int smem_set = 0;
    if (!smem_set) {
        cudaFuncSetAttribute(lstm_layer_k, cudaFuncAttributeMaxDynamicSharedMemorySize, SMEM12);
        smem_set = 1;
    }

    // setup — layer-1 GEMM is 4th launch (ncu -s 5 visibility window)
    embed_k<<<(TSZ * BSZ * ESZ + 255) / 256, 256>>>(emb, x, y0);
    wtrans_k<<<dim3(GP12 / 32, (HSZ + 31) / 32), dim3(32, 8)>>>(Whh1, Wt1, HSZ, GP12);
    wtrans_k<<<dim3(GP12 / 32, (HSZ + 31) / 32), dim3(32, 8)>>>(Whh2, Wt2, HSZ, GP12);
    gemm_tc<<<dim3((4 * HSZ + 127) / 128, M / 128), 256>>>(y0, Wih1, bih1, bhh1, pre,
                                                           M, 4 * HSZ, ESZ, 0);
    wtrans_k<<<dim3(GP3 / 32, (ESZ + 31) / 32), dim3(32, 8)>>>(Whh3, Wt3, ESZ, GP3);
    pad_k<<<(4 * HSZ * HPAD + 255) / 256, 256>>>(Wih2, W2p, 4 * HSZ, HSZ, HPAD);
    pad_k<<<(4 * ESZ * HPAD + 255) / 256, 256>>>(Wih3, W3p, 4 * ESZ, HSZ, HPAD);
    zero_k<<<1, 4>>>((float*)bar, 4);

    // ----- layer 1 recurrence (persistent) -----
    lstm_layer_k<<<GP12 / 32, 256, SMEM12>>>(pre, Wt1, hTa, hTb, cT1, y1,
                                             HSZ, GP12, HPAD, bar + 0);

    // ----- layer 2 -----
    gemm_tc<<<dim3((4 * HSZ + 127) / 128, M / 128), 256>>>(y1, W2p, bih2, bhh2, pre,
                                                           M, 4 * HSZ, HPAD, 0);
    lstm_layer_k<<<GP12 / 32, 256, SMEM12>>>(pre, Wt2, hTa, hTb, cT2, y2,
                                             HSZ, GP12, HPAD, bar + 1);

    // ----- layer 3 -----
    gemm_tc<<<dim3((4 * ESZ + 127) / 128, M / 128), 256>>>(y2, W3p, bih3, bhh3, pre,
                                                           M, 4 * ESZ, HPAD, 0);
    lstm_layer_k<<<GP3 / 32, 256, SMEM3>>>(pre, Wt3, hTa, hTb, cT3, y3,
                                           ESZ, GP3, ESZ, bar + 2);

    // ----- tied output projection into (B,V,T) -----
    gemm_tc<<<dim3(VSZ / 128, M / 128), 256>>>(y3, emb, linb, nullptr, out,
                                               M, VSZ, ESZ, 1);

    // ----- final states -----
    finalize_k<<<(86400 + 255) / 256, 256>>>(y1, y2, y3, cT1, cT2, cT3, out);
}

// round 6
// speedup vs baseline: 1.2090x; 1.2090x over previous
#include <cuda_runtime.h>
#include <math.h>

#define VSZ 32000
#define ESZ 400
#define HSZ 1150
#define HPAD 1152
#define BSZ 16
#define TSZ 128
#define GP12 4608   // padded gate-col count for layers 1/2 (144 CTAs * 32)
#define GP3  1600   // layer 3 gate cols (50 CTAs * 32)

// ---------------- scratch (device globals; no allocation allowed) ----------------
__device__ float g_y0[TSZ*BSZ*ESZ];
__device__ float g_y1[TSZ*BSZ*HPAD];
__device__ float g_y2[TSZ*BSZ*HPAD];
__device__ float g_y3[TSZ*BSZ*ESZ];
__device__ float g_pre[TSZ*BSZ*4*HSZ];
__device__ float g_Wt1[HSZ*GP12];
__device__ float g_Wt2[HSZ*GP12];
__device__ float g_Wt3[ESZ*GP3];
__device__ float g_Wih2p[4*HSZ*HPAD];
__device__ float g_Wih3p[4*ESZ*HPAD];
__device__ float g_hTa[HSZ*BSZ];
__device__ float g_hTb[HSZ*BSZ];
__device__ float g_cT1[HSZ*BSZ];
__device__ float g_cT2[HSZ*BSZ];
__device__ float g_cT3[ESZ*BSZ];
__device__ unsigned g_bar[4];

// ---------------- tiny utility kernels ----------------
__global__ void zero_k(float* __restrict__ p, int n) {
    int i = blockIdx.x * blockDim.x + threadIdx.x;
    if (i < n) p[i] = 0.f;
}

__global__ void pad_k(const float* __restrict__ src, float* __restrict__ dst,
                      int rows, int Kin, int Kout) {
    int idx = blockIdx.x * blockDim.x + threadIdx.x;
    if (idx >= rows * Kout) return;
    int r = idx / Kout, k = idx % Kout;
    dst[idx] = (k < Kin) ? src[(size_t)r * Kin + k] : 0.f;
}

__global__ void embed_k(const float* __restrict__ emb, const int* __restrict__ x,
                        float* __restrict__ y0) {
    int idx = blockIdx.x * blockDim.x + threadIdx.x;
    if (idx >= TSZ * BSZ * ESZ) return;
    int e   = idx % ESZ;
    int row = idx / ESZ;      // b*T + t
    y0[idx] = emb[(size_t)x[row] * ESZ + e];
}

// Gate-permuted transpose of W_hh
__global__ void wtrans_k(const float* __restrict__ W, float* __restrict__ Wt,
                         int Hp, int Gp) {
    __shared__ float tile[32][33];
    int jblk = blockIdx.x;
    int k0   = blockIdx.y * 32;
    for (int rr = 0; rr < 32; rr += 8) {
        int r = rr + threadIdx.y;
        int g = r >> 3, u = r & 7;
        int j = jblk * 8 + u;
        int orow = g * Hp + j;
        int k = k0 + threadIdx.x;
        tile[r][threadIdx.x] = (j < Hp && k < Hp) ? W[(size_t)orow * Hp + k] : 0.f;
    }
    __syncthreads();
    for (int kk = 0; kk < 32; kk += 8) {
        int k = k0 + kk + threadIdx.y;
        if (k < Hp)
            Wt[(size_t)k * Gp + jblk * 32 + threadIdx.x] = tile[threadIdx.x][kk + threadIdx.y];
    }
}

// ---------------- tf32x2 tensor-core GEMM ----------------
__device__ __forceinline__ float tf32_rna(float x) {
    float r;
    asm("cvt.rna.tf32.f32 %0, %1;" : "=f"(r) : "f"(x));
    return r;
}

__device__ __forceinline__ void mma_tf32(float4& d, const float* a, const float* b) {
    asm volatile(
        "mma.sync.aligned.m16n8k8.row.col.f32.tf32.tf32.f32 "
        "{%0,%1,%2,%3}, {%4,%5,%6,%7}, {%8,%9}, {%0,%1,%2,%3};\n"
        : "+f"(d.x), "+f"(d.y), "+f"(d.z), "+f"(d.w)
        : "r"(__float_as_uint(a[0])), "r"(__float_as_uint(a[1])),
          "r"(__float_as_uint(a[2])), "r"(__float_as_uint(a[3])),
          "r"(__float_as_uint(b[0])), "r"(__float_as_uint(b[1])));
}

#define SSTR 20

__global__ __launch_bounds__(256)
void gemm_tc(const float* __restrict__ A, const float* __restrict__ Bm,
             const float* __restrict__ bias1, const float* __restrict__ bias2,
             float* __restrict__ C, int M, int N, int K, int mode) {
    __shared__ float As[2][128 * SSTR];
    __shared__ float Bs[2][128 * SSTR];

    const int tid  = threadIdx.x;
    const int lane = tid & 31;
    const int w    = tid >> 5;
    const int wm   = (w & 1) * 64;
    const int wn   = (w >> 1) * 32;
    const int qr   = lane >> 2;
    const int qc   = lane & 3;

    const int m0 = blockIdx.y * 128;
    const int n0 = blockIdx.x * 128;

    const int lrow = tid >> 1;
    const int lk   = (tid & 1) * 8;

    const float* Aptr = A + (size_t)(m0 + lrow) * K + lk;
    const float* Bptr = Bm + (size_t)(n0 + lrow) * K + lk;
    const bool bvalid = (n0 + lrow) < N;

    float4 acc[4][4];
#pragma unroll
    for (int i = 0; i < 4; i++)
#pragma unroll
        for (int j = 0; j < 4; j++) acc[i][j] = make_float4(0.f, 0.f, 0.f, 0.f);

    for (int k0 = 0; k0 < K; k0 += 16) {
        float4 av0 = *(const float4*)(Aptr + k0);
        float4 av1 = *(const float4*)(Aptr + k0 + 4);
        float4 bv0 = bvalid ? *(const float4*)(Bptr + k0) : make_float4(0.f, 0.f, 0.f, 0.f);
        float4 bv1 = bvalid ? *(const float4*)(Bptr + k0 + 4) : make_float4(0.f, 0.f, 0.f, 0.f);
        __syncthreads();
        {
            float va[8] = {av0.x, av0.y, av0.z, av0.w, av1.x, av1.y, av1.z, av1.w};
            float vb[8] = {bv0.x, bv0.y, bv0.z, bv0.w, bv1.x, bv1.y, bv1.z, bv1.w};
            int base = lrow * SSTR + lk;
#pragma unroll
            for (int j = 0; j < 8; j++) {
                float hi = tf32_rna(va[j]);
                As[0][base + j] = hi;
                As[1][base + j] = tf32_rna(va[j] - hi);
                float bhi = tf32_rna(vb[j]);
                Bs[0][base + j] = bhi;
                Bs[1][base + j] = tf32_rna(vb[j] - bhi);
            }
        }
        __syncthreads();

#pragma unroll
        for (int kk = 0; kk < 16; kk += 8) {
            float ah[4][4], al[4][4], bh[4][2], bl[4][2];
#pragma unroll
            for (int mt = 0; mt < 4; mt++) {
                int base = (wm + mt * 16 + qr) * SSTR + kk + qc;
                ah[mt][0] = As[0][base];
                ah[mt][1] = As[0][base + 8 * SSTR];
                ah[mt][2] = As[0][base + 4];
                ah[mt][3] = As[0][base + 8 * SSTR + 4];
                al[mt][0] = As[1][base];
                al[mt][1] = As[1][base + 8 * SSTR];
                al[mt][2] = As[1][base + 4];
                al[mt][3] = As[1][base + 8 * SSTR + 4];
            }
#pragma unroll
            for (int nt = 0; nt < 4; nt++) {
                int base = (wn + nt * 8 + qr) * SSTR + kk + qc;
                bh[nt][0] = Bs[0][base];
                bh[nt][1] = Bs[0][base + 4];
                bl[nt][0] = Bs[1][base];
                bl[nt][1] = Bs[1][base + 4];
            }
#pragma unroll
            for (int mt = 0; mt < 4; mt++)
#pragma unroll
                for (int nt = 0; nt < 4; nt++) {
                    mma_tf32(acc[mt][nt], ah[mt], bh[nt]);
                    mma_tf32(acc[mt][nt], ah[mt], bl[nt]);
                    mma_tf32(acc[mt][nt], al[mt], bh[nt]);
                }
        }
    }

#pragma unroll
    for (int mt = 0; mt < 4; mt++) {
        int mrow = m0 + wm + mt * 16 + qr;
#pragma unroll
        for (int nt = 0; nt < 4; nt++) {
            int n = n0 + wn + nt * 8 + 2 * qc;
            if (n >= N) continue;
            float b0 = 0.f, b1 = 0.f;
            if (bias1) { b0 += bias1[n]; b1 += bias1[n + 1]; }
            if (bias2) { b0 += bias2[n]; b1 += bias2[n + 1]; }
            float4 v = acc[mt][nt];
            if (mode == 0) {
                C[(size_t)mrow * N + n]           = v.x + b0;
                C[(size_t)mrow * N + n + 1]       = v.y + b1;
                C[(size_t)(mrow + 8) * N + n]     = v.z + b0;
                C[(size_t)(mrow + 8) * N + n + 1] = v.w + b1;
            } else {
                int bidx = m0 >> 7;
                int t = (mrow - m0);
                size_t base = ((size_t)bidx * N + n) * TSZ + t;
                C[base]           = v.x + b0;
                C[base + TSZ]     = v.y + b1;
                C[base + 8]       = v.z + b0;
                C[base + TSZ + 8] = v.w + b1;
            }
        }
    }
}

// ---------------- persistent LSTM layer kernel ----------------
// Lane mapping: lane = bg*8 + cg. Each thread covers 4 cols (cg*4..+3) x 4 batches
// (bg*4..+3), so per k-iter: 1 LDG.128 (h, 4 batches) + 1 LDS.128 (4 weights) + 8 FMA2.
__device__ __forceinline__ float sigf(float z) { return 1.f / (1.f + expf(-z)); }

#define FMA2(d, a, b) \
    asm("fma.rn.f32x2 %0, %1, %2, %0;" : "+l"(d) : "l"(a), "l"(b))

__device__ __forceinline__ void grid_bar(unsigned* bar, unsigned target) {
    __syncthreads();
    if (threadIdx.x == 0) {
        __threadfence();
        atomicAdd(bar, 1u);
        while (*(volatile unsigned*)bar < target) __nanosleep(64);
        __threadfence();
    }
    __syncthreads();
}

__global__ __launch_bounds__(256, 1)
void lstm_layer_k(const float* __restrict__ pre, const float* __restrict__ Wt,
                  float* __restrict__ hA, float* __restrict__ hB,
                  float* __restrict__ cOut, float* __restrict__ y,
                  int Hp, int Gp, int ldy, unsigned* bar) {
    extern __shared__ float sm[];
    float* sW  = sm;                 // Hp*32
    float* red = sm + Hp * 32;       // 8*32*16 = 4096
    float* cT  = red + 4096;         // 128

    const int tid  = threadIdx.x;
    const int jblk = blockIdx.x;
    const int nCTA = gridDim.x;
    const int lane = tid & 31;
    const int s    = tid >> 5;       // k-slice 0..7
    const int bg   = lane >> 3;      // batch group 0..3
    const int cg   = lane & 7;       // col group 0..7 (4 cols each)
    const int G4 = 4 * Hp;

    // epilogue thread mapping
    const int eu = tid >> 4;            // unit within block (tid<128 -> 0..7)
    const int eb = tid & 15;            // batch
    const int ej = jblk * 8 + eu;
    const bool eact = (tid < 128) && (ej < Hp);
    const bool epad = (tid < 128) && (ej >= Hp) && (ej < ldy);
    const int ebg = eb >> 2, ebi = eb & 3;

    // stage weights into smem (coalesced)
    for (int idx = tid; idx < Hp * 32; idx += 256) {
        int k = idx >> 5, rr = idx & 31;
        sW[idx] = Wt[(size_t)k * Gp + jblk * 32 + rr];
    }
    if (tid < 128) {
        cT[tid] = 0.f;
        if (ej < Hp) hA[ej * 16 + eb] = 0.f;
    }
    grid_bar(bar, (unsigned)nCTA);

    const float4* sW4base = (const float4*)sW;

    for (int t = 0; t < TSZ; t++) {
        const float* hin = (t & 1) ? hB : hA;
        float* hout      = (t & 1) ? hA : hB;

        // prefetch pre-activation gate values early (independent of h)
        float pg[4];
        size_t erow = (size_t)eb * TSZ + t;
        if (eact) {
            const float* prow = pre + erow * G4 + ej;
#pragma unroll
            for (int g = 0; g < 4; g++) pg[g] = __ldcg(prow + (size_t)g * Hp);
        }

        unsigned long long acc2[8];   // [c 0..3][batch-pair 0..1]
#pragma unroll
        for (int i = 0; i < 8; i++) acc2[i] = 0ULL;

        const ulonglong2* hv = (const ulonglong2*)hin;  // h[k*16+b]
#pragma unroll 4
        for (int k = s; k < Hp; k += 8) {
            float4 wq = sW4base[k * 8 + cg];
            ulonglong2 hp = hv[k * 4 + bg];
            unsigned long long w0, w1, w2, w3;
            asm("mov.b64 %0, {%1, %1};" : "=l"(w0) : "r"(__float_as_uint(wq.x)));
            asm("mov.b64 %0, {%1, %1};" : "=l"(w1) : "r"(__float_as_uint(wq.y)));
            asm("mov.b64 %0, {%1, %1};" : "=l"(w2) : "r"(__float_as_uint(wq.z)));
            asm("mov.b64 %0, {%1, %1};" : "=l"(w3) : "r"(__float_as_uint(wq.w)));
            FMA2(acc2[0], w0, hp.x); FMA2(acc2[1], w0, hp.y);
            FMA2(acc2[2], w1, hp.x); FMA2(acc2[3], w1, hp.y);
            FMA2(acc2[4], w2, hp.x); FMA2(acc2[5], w2, hp.y);
            FMA2(acc2[6], w3, hp.x); FMA2(acc2[7], w3, hp.y);
        }

        // red[(s*32 + lane)*16 + c*4 + bi] = partial(col cg*4+c, batch bg*4+bi)
        ulonglong2* rp = (ulonglong2*)&red[(s * 32 + lane) * 16];
        rp[0] = make_ulonglong2(acc2[0], acc2[1]);
        rp[1] = make_ulonglong2(acc2[2], acc2[3]);
        rp[2] = make_ulonglong2(acc2[4], acc2[5]);
        rp[3] = make_ulonglong2(acc2[6], acc2[7]);
        __syncthreads();

        if (eact) {
            float gv[4];
#pragma unroll
            for (int g = 0; g < 4; g++) {
                int co  = g * 8 + eu;
                int cg2 = co >> 2, c2 = co & 3;
                float sum = pg[g];
#pragma unroll
                for (int s2 = 0; s2 < 8; s2++)
                    sum += red[(s2 * 32 + ebg * 8 + cg2) * 16 + c2 * 4 + ebi];
                gv[g] = sum;
            }
            float ig = sigf(gv[0]);
            float fg = sigf(gv[1]);
            float gg = tanhf(gv[2]);
            float og = sigf(gv[3]);
            float c  = fg * cT[tid] + ig * gg;
            float hn = og * tanhf(c);
            cT[tid] = c;
            hout[ej * 16 + eb] = hn;
            y[erow * ldy + ej] = hn;
            if (t == TSZ - 1) cOut[ej * 16 + eb] = c;
        } else if (epad) {
            y[erow * ldy + ej] = 0.f;
        }
        grid_bar(bar, (unsigned)(nCTA * (t + 2)));
    }
}

// ---------------- finalize ----------------
__global__ void finalize_k(const float* __restrict__ y1, const float* __restrict__ y2,
                           const float* __restrict__ y3, const float* __restrict__ cT1,
                           const float* __restrict__ cT2, const float* __restrict__ cT3,
                           float* __restrict__ out) {
    int i = blockIdx.x * blockDim.x + threadIdx.x;
    if (i >= 86400) return;
    const size_t O = (size_t)BSZ * VSZ * TSZ;
    if (i < 18400) {
        int b = i / 1150, j = i % 1150;
        out[O + i] = y1[((size_t)b * TSZ + 127) * HPAD + j];
    } else if (i < 36800) {
        int k = i - 18400; int b = k / 1150, j = k % 1150;
        out[O + i] = y2[((size_t)b * TSZ + 127) * HPAD + j];
    } else if (i < 43200) {
        int k = i - 36800; int b = k / 400, j = k % 400;
        out[O + i] = y3[((size_t)b * TSZ + 127) * 400 + j];
    } else if (i < 61600) {
        int k = i - 43200; int j = (k % 1150), b = k / 1150;
        out[O + i] = cT1[j * 16 + b];
    } else if (i < 80000) {
        int k = i - 61600; int j = (k % 1150), b = k / 1150;
        out[O + i] = cT2[j * 16 + b];
    } else {
        int k = i - 80000; int j = (k % 400), b = k / 400;
        out[O + i] = cT3[j * 16 + b];
    }
}

// ---------------- launch ----------------
extern "C" void kernel_launch(void* const* d_in, const int* in_sizes, int n_in,
                              void* d_out, int out_size) {
    const float* emb  = (const float*)d_in[0];
    const float* Wih1 = (const float*)d_in[1];
    const float* Whh1 = (const float*)d_in[2];
    const float* bih1 = (const float*)d_in[3];
    const float* bhh1 = (const float*)d_in[4];
    const float* Wih2 = (const float*)d_in[5];
    const float* Whh2 = (const float*)d_in[6];
    const float* bih2 = (const float*)d_in[7];
    const float* bhh2 = (const float*)d_in[8];
    const float* Wih3 = (const float*)d_in[9];
    const float* Whh3 = (const float*)d_in[10];
    const float* bih3 = (const float*)d_in[11];
    const float* bhh3 = (const float*)d_in[12];
    const float* linb = (const float*)d_in[13];
    const int*   x    = (const int*)d_in[14];
    float* out = (float*)d_out;

    float *y0, *y1, *y2, *y3, *pre, *Wt1, *Wt2, *Wt3, *W2p, *W3p;
    float *hTa, *hTb, *cT1, *cT2, *cT3;
    unsigned* bar;
    cudaGetSymbolAddress((void**)&y0,  g_y0);
    cudaGetSymbolAddress((void**)&y1,  g_y1);
    cudaGetSymbolAddress((void**)&y2,  g_y2);
    cudaGetSymbolAddress((void**)&y3,  g_y3);
    cudaGetSymbolAddress((void**)&pre, g_pre);
    cudaGetSymbolAddress((void**)&Wt1, g_Wt1);
    cudaGetSymbolAddress((void**)&Wt2, g_Wt2);
    cudaGetSymbolAddress((void**)&Wt3, g_Wt3);
    cudaGetSymbolAddress((void**)&W2p, g_Wih2p);
    cudaGetSymbolAddress((void**)&W3p, g_Wih3p);
    cudaGetSymbolAddress((void**)&hTa, g_hTa);
    cudaGetSymbolAddress((void**)&hTb, g_hTb);
    cudaGetSymbolAddress((void**)&cT1, g_cT1);
    cudaGetSymbolAddress((void**)&cT2, g_cT2);
    cudaGetSymbolAddress((void**)&cT3, g_cT3);
    cudaGetSymbolAddress((void**)&bar, g_bar);

    const int M = TSZ * BSZ;  // 2048
    const int SMEM12 = (HSZ * 32 + 4096 + 128) * 4;  // 164096 B
    const int SMEM3  = (ESZ * 32 + 4096 + 128) * 4;  //  68096 B
    static int smem_set = 0;
    if (!smem_set) {
        cudaFuncSetAttribute(lstm_layer_k, cudaFuncAttributeMaxDynamicSharedMemorySize, SMEM12);
        smem_set = 1;
    }

    // setup — layer-1 GEMM is 4th launch (ncu -s 5 visibility window)
    embed_k<<<(TSZ * BSZ * ESZ + 255) / 256, 256>>>(emb, x, y0);
    wtrans_k<<<dim3(GP12 / 32, (HSZ + 31) / 32), dim3(32, 8)>>>(Whh1, Wt1, HSZ, GP12);
    wtrans_k<<<dim3(GP12 / 32, (HSZ + 31) / 32), dim3(32, 8)>>>(Whh2, Wt2, HSZ, GP12);
    gemm_tc<<<dim3((4 * HSZ + 127) / 128, M / 128), 256>>>(y0, Wih1, bih1, bhh1, pre,
                                                           M, 4 * HSZ, ESZ, 0);
    wtrans_k<<<dim3(GP3 / 32, (ESZ + 31) / 32), dim3(32, 8)>>>(Whh3, Wt3, ESZ, GP3);
    pad_k<<<(4 * HSZ * HPAD + 255) / 256, 256>>>(Wih2, W2p, 4 * HSZ, HSZ, HPAD);
    pad_k<<<(4 * ESZ * HPAD + 255) / 256, 256>>>(Wih3, W3p, 4 * ESZ, HSZ, HPAD);
    zero_k<<<1, 4>>>((float*)bar, 4);

    // ----- layer 1 recurrence (persistent) -----
    lstm_layer_k<<<GP12 / 32, 256, SMEM12>>>(pre, Wt1, hTa, hTb, cT1, y1,
                                             HSZ, GP12, HPAD, bar + 0);

    // ----- layer 2 -----
    gemm_tc<<<dim3((4 * HSZ + 127) / 128, M / 128), 256>>>(y1, W2p, bih2, bhh2, pre,
                                                           M, 4 * HSZ, HPAD, 0);
    lstm_layer_k<<<GP12 / 32, 256, SMEM12>>>(pre, Wt2, hTa, hTb, cT2, y2,
                                             HSZ, GP12, HPAD, bar + 1);

    // ----- layer 3 -----
    gemm_tc<<<dim3((4 * ESZ + 127) / 128, M / 128), 256>>>(y2, W3p, bih3, bhh3, pre,
                                                           M, 4 * ESZ, HPAD, 0);
    lstm_layer_k<<<GP3 / 32, 256, SMEM3>>>(pre, Wt3, hTa, hTb, cT3, y3,
                                           ESZ, GP3, ESZ, bar + 2);

    // ----- tied output projection into (B,V,T) -----
    gemm_tc<<<dim3(VSZ / 128, M / 128), 256>>>(y3, emb, linb, nullptr, out,
                                               M, VSZ, ESZ, 1);

    // ----- final states -----
    finalize_k<<<(86400 + 255) / 256, 256>>>(y1, y2, y3, cT1, cT2, cT3, out);
}

// round 7
// speedup vs baseline: 1.2213x; 1.0102x over previous
#include <cuda_runtime.h>
#include <math.h>

#define VSZ 32000
#define ESZ 400
#define HSZ 1150
#define HPAD 1152
#define BSZ 16
#define TSZ 128
#define GP12 4608   // padded gate-col count for layers 1/2 (144 CTAs * 32)
#define GP3  1600   // layer 3 gate cols (50 CTAs * 32)
#define FLAGSTRIDE 32   // 128B per CTA flag line

// ---------------- scratch (device globals; no allocation allowed) ----------------
__device__ float g_y0[TSZ*BSZ*ESZ];
__device__ float g_y1[TSZ*BSZ*HPAD];
__device__ float g_y2[TSZ*BSZ*HPAD];
__device__ float g_y3[TSZ*BSZ*ESZ];
__device__ float g_pre[TSZ*BSZ*4*HSZ];
__device__ float g_Wt1[HSZ*GP12];
__device__ float g_Wt2[HSZ*GP12];
__device__ float g_Wt3[ESZ*GP3];
__device__ float g_Wih2p[4*HSZ*HPAD];
__device__ float g_Wih3p[4*ESZ*HPAD];
__device__ float g_hTa[HSZ*BSZ];
__device__ float g_hTb[HSZ*BSZ];
__device__ float g_cT1[HSZ*BSZ];
__device__ float g_cT2[HSZ*BSZ];
__device__ float g_cT3[ESZ*BSZ];
__device__ unsigned g_flags[3 * 144 * FLAGSTRIDE];

// ---------------- tiny utility kernels ----------------
__global__ void zero_k(float* __restrict__ p, int n) {
    int i = blockIdx.x * blockDim.x + threadIdx.x;
    if (i < n) p[i] = 0.f;
}

__global__ void pad_k(const float* __restrict__ src, float* __restrict__ dst,
                      int rows, int Kin, int Kout) {
    int idx = blockIdx.x * blockDim.x + threadIdx.x;
    if (idx >= rows * Kout) return;
    int r = idx / Kout, k = idx % Kout;
    dst[idx] = (k < Kin) ? src[(size_t)r * Kin + k] : 0.f;
}

// embedding gather + zero the barrier flags (must precede all lstm layers)
__global__ void embed_k(const float* __restrict__ emb, const int* __restrict__ x,
                        float* __restrict__ y0, unsigned* __restrict__ flags) {
    int idx = blockIdx.x * blockDim.x + threadIdx.x;
    if (idx < 3 * 144 * FLAGSTRIDE) flags[idx] = 0u;
    if (idx >= TSZ * BSZ * ESZ) return;
    int e   = idx % ESZ;
    int row = idx / ESZ;      // b*T + t
    y0[idx] = emb[(size_t)x[row] * ESZ + e];
}

// Gate-permuted transpose of W_hh
__global__ void wtrans_k(const float* __restrict__ W, float* __restrict__ Wt,
                         int Hp, int Gp) {
    __shared__ float tile[32][33];
    int jblk = blockIdx.x;
    int k0   = blockIdx.y * 32;
    for (int rr = 0; rr < 32; rr += 8) {
        int r = rr + threadIdx.y;
        int g = r >> 3, u = r & 7;
        int j = jblk * 8 + u;
        int orow = g * Hp + j;
        int k = k0 + threadIdx.x;
        tile[r][threadIdx.x] = (j < Hp && k < Hp) ? W[(size_t)orow * Hp + k] : 0.f;
    }
    __syncthreads();
    for (int kk = 0; kk < 32; kk += 8) {
        int k = k0 + kk + threadIdx.y;
        if (k < Hp)
            Wt[(size_t)k * Gp + jblk * 32 + threadIdx.x] = tile[threadIdx.x][kk + threadIdx.y];
    }
}

// ---------------- tf32x2 tensor-core GEMM ----------------
__device__ __forceinline__ float tf32_rna(float x) {
    float r;
    asm("cvt.rna.tf32.f32 %0, %1;" : "=f"(r) : "f"(x));
    return r;
}

__device__ __forceinline__ void mma_tf32(float4& d, const float* a, const float* b) {
    asm volatile(
        "mma.sync.aligned.m16n8k8.row.col.f32.tf32.tf32.f32 "
        "{%0,%1,%2,%3}, {%4,%5,%6,%7}, {%8,%9}, {%0,%1,%2,%3};\n"
        : "+f"(d.x), "+f"(d.y), "+f"(d.z), "+f"(d.w)
        : "r"(__float_as_uint(a[0])), "r"(__float_as_uint(a[1])),
          "r"(__float_as_uint(a[2])), "r"(__float_as_uint(a[3])),
          "r"(__float_as_uint(b[0])), "r"(__float_as_uint(b[1])));
}

#define SSTR 20

__global__ __launch_bounds__(256)
void gemm_tc(const float* __restrict__ A, const float* __restrict__ Bm,
             const float* __restrict__ bias1, const float* __restrict__ bias2,
             float* __restrict__ C, int M, int N, int K, int mode) {
    __shared__ float As[2][128 * SSTR];
    __shared__ float Bs[2][128 * SSTR];

    const int tid  = threadIdx.x;
    const int lane = tid & 31;
    const int w    = tid >> 5;
    const int wm   = (w & 1) * 64;
    const int wn   = (w >> 1) * 32;
    const int qr   = lane >> 2;
    const int qc   = lane & 3;

    const int m0 = blockIdx.y * 128;
    const int n0 = blockIdx.x * 128;

    const int lrow = tid >> 1;
    const int lk   = (tid & 1) * 8;

    const float* Aptr = A + (size_t)(m0 + lrow) * K + lk;
    const float* Bptr = Bm + (size_t)(n0 + lrow) * K + lk;
    const bool bvalid = (n0 + lrow) < N;

    float4 acc[4][4];
#pragma unroll
    for (int i = 0; i < 4; i++)
#pragma unroll
        for (int j = 0; j < 4; j++) acc[i][j] = make_float4(0.f, 0.f, 0.f, 0.f);

    for (int k0 = 0; k0 < K; k0 += 16) {
        float4 av0 = *(const float4*)(Aptr + k0);
        float4 av1 = *(const float4*)(Aptr + k0 + 4);
        float4 bv0 = bvalid ? *(const float4*)(Bptr + k0) : make_float4(0.f, 0.f, 0.f, 0.f);
        float4 bv1 = bvalid ? *(const float4*)(Bptr + k0 + 4) : make_float4(0.f, 0.f, 0.f, 0.f);
        __syncthreads();
        {
            float va[8] = {av0.x, av0.y, av0.z, av0.w, av1.x, av1.y, av1.z, av1.w};
            float vb[8] = {bv0.x, bv0.y, bv0.z, bv0.w, bv1.x, bv1.y, bv1.z, bv1.w};
            int base = lrow * SSTR + lk;
#pragma unroll
            for (int j = 0; j < 8; j++) {
                float hi = tf32_rna(va[j]);
                As[0][base + j] = hi;
                As[1][base + j] = tf32_rna(va[j] - hi);
                float bhi = tf32_rna(vb[j]);
                Bs[0][base + j] = bhi;
                Bs[1][base + j] = tf32_rna(vb[j] - bhi);
            }
        }
        __syncthreads();

#pragma unroll
        for (int kk = 0; kk < 16; kk += 8) {
            float ah[4][4], al[4][4], bh[4][2], bl[4][2];
#pragma unroll
            for (int mt = 0; mt < 4; mt++) {
                int base = (wm + mt * 16 + qr) * SSTR + kk + qc;
                ah[mt][0] = As[0][base];
                ah[mt][1] = As[0][base + 8 * SSTR];
                ah[mt][2] = As[0][base + 4];
                ah[mt][3] = As[0][base + 8 * SSTR + 4];
                al[mt][0] = As[1][base];
                al[mt][1] = As[1][base + 8 * SSTR];
                al[mt][2] = As[1][base + 4];
                al[mt][3] = As[1][base + 8 * SSTR + 4];
            }
#pragma unroll
            for (int nt = 0; nt < 4; nt++) {
                int base = (wn + nt * 8 + qr) * SSTR + kk + qc;
                bh[nt][0] = Bs[0][base];
                bh[nt][1] = Bs[0][base + 4];
                bl[nt][0] = Bs[1][base];
                bl[nt][1] = Bs[1][base + 4];
            }
#pragma unroll
            for (int mt = 0; mt < 4; mt++)
#pragma unroll
                for (int nt = 0; nt < 4; nt++) {
                    mma_tf32(acc[mt][nt], ah[mt], bh[nt]);
                    mma_tf32(acc[mt][nt], ah[mt], bl[nt]);
                    mma_tf32(acc[mt][nt], al[mt], bh[nt]);
                }
        }
    }

#pragma unroll
    for (int mt = 0; mt < 4; mt++) {
        int mrow = m0 + wm + mt * 16 + qr;
#pragma unroll
        for (int nt = 0; nt < 4; nt++) {
            int n = n0 + wn + nt * 8 + 2 * qc;
            if (n >= N) continue;
            float b0 = 0.f, b1 = 0.f;
            if (bias1) { b0 += bias1[n]; b1 += bias1[n + 1]; }
            if (bias2) { b0 += bias2[n]; b1 += bias2[n + 1]; }
            float4 v = acc[mt][nt];
            if (mode == 0) {
                C[(size_t)mrow * N + n]           = v.x + b0;
                C[(size_t)mrow * N + n + 1]       = v.y + b1;
                C[(size_t)(mrow + 8) * N + n]     = v.z + b0;
                C[(size_t)(mrow + 8) * N + n + 1] = v.w + b1;
            } else {
                int bidx = m0 >> 7;
                int t = (mrow - m0);
                size_t base = ((size_t)bidx * N + n) * TSZ + t;
                C[base]           = v.x + b0;
                C[base + TSZ]     = v.y + b1;
                C[base + 8]       = v.z + b0;
                C[base + TSZ + 8] = v.w + b1;
            }
        }
    }
}

// ---------------- persistent LSTM layer kernel ----------------
__device__ __forceinline__ float sigf(float z) { return 1.f / (1.f + expf(-z)); }

#define FMA2(d, a, b) \
    asm("fma.rn.f32x2 %0, %1, %2, %0;" : "+l"(d) : "l"(a), "l"(b))

// distributed flag barrier: one 128B line per CTA; parallel polling.
__device__ __forceinline__ void grid_bar_flags(unsigned* flags, int nCTA, unsigned phase) {
    __syncthreads();
    if (threadIdx.x == 0) {
        asm volatile("st.release.gpu.global.u32 [%0], %1;"
                     :: "l"(flags + (size_t)blockIdx.x * FLAGSTRIDE), "r"(phase) : "memory");
    }
    if (threadIdx.x < nCTA) {
        unsigned v;
        do {
            asm volatile("ld.acquire.gpu.global.u32 %0, [%1];"
                         : "=r"(v) : "l"(flags + (size_t)threadIdx.x * FLAGSTRIDE) : "memory");
        } while (v < phase);
    }
    __syncthreads();
}

__global__ __launch_bounds__(256, 1)
void lstm_layer_k(const float* __restrict__ pre, const float* __restrict__ Wt,
                  float* __restrict__ hA, float* __restrict__ hB,
                  float* __restrict__ cOut, float* __restrict__ y,
                  int Hp, int Gp, int ldy, unsigned* flags) {
    extern __shared__ float sm[];
    float* sW  = sm;                 // Hp*32
    float* red = sm + Hp * 32;       // 8*32*16 = 4096
    float* cT  = red + 4096;         // 128

    const int tid  = threadIdx.x;
    const int jblk = blockIdx.x;
    const int nCTA = gridDim.x;
    const int lane = tid & 31;
    const int s    = tid >> 5;       // k-slice 0..7
    const int bg   = lane >> 3;      // batch group 0..3
    const int cg   = lane & 7;       // col group 0..7 (4 cols each)
    const int G4 = 4 * Hp;

    const int eu = tid >> 4;            // unit within block (tid<128 -> 0..7)
    const int eb = tid & 15;            // batch
    const int ej = jblk * 8 + eu;
    const bool eact = (tid < 128) && (ej < Hp);
    const bool epad = (tid < 128) && (ej >= Hp) && (ej < ldy);
    const int ebg = eb >> 2, ebi = eb & 3;

    for (int idx = tid; idx < Hp * 32; idx += 256) {
        int k = idx >> 5, rr = idx & 31;
        sW[idx] = Wt[(size_t)k * Gp + jblk * 32 + rr];
    }
    if (tid < 128) {
        cT[tid] = 0.f;
        if (ej < Hp) hA[ej * 16 + eb] = 0.f;
    }
    grid_bar_flags(flags, nCTA, 1u);

    const float4* sW4base = (const float4*)sW;

    for (int t = 0; t < TSZ; t++) {
        const float* hin = (t & 1) ? hB : hA;
        float* hout      = (t & 1) ? hA : hB;

        float pg[4];
        size_t erow = (size_t)eb * TSZ + t;
        if (eact) {
            const float* prow = pre + erow * G4 + ej;
#pragma unroll
            for (int g = 0; g < 4; g++) pg[g] = __ldcg(prow + (size_t)g * Hp);
        }

        unsigned long long acc2[8];
#pragma unroll
        for (int i = 0; i < 8; i++) acc2[i] = 0ULL;

        const ulonglong2* hv = (const ulonglong2*)hin;
#pragma unroll 4
        for (int k = s; k < Hp; k += 8) {
            float4 wq = sW4base[k * 8 + cg];
            ulonglong2 hp = hv[k * 4 + bg];
            unsigned long long w0, w1, w2, w3;
            asm("mov.b64 %0, {%1, %1};" : "=l"(w0) : "r"(__float_as_uint(wq.x)));
            asm("mov.b64 %0, {%1, %1};" : "=l"(w1) : "r"(__float_as_uint(wq.y)));
            asm("mov.b64 %0, {%1, %1};" : "=l"(w2) : "r"(__float_as_uint(wq.z)));
            asm("mov.b64 %0, {%1, %1};" : "=l"(w3) : "r"(__float_as_uint(wq.w)));
            FMA2(acc2[0], w0, hp.x); FMA2(acc2[1], w0, hp.y);
            FMA2(acc2[2], w1, hp.x); FMA2(acc2[3], w1, hp.y);
            FMA2(acc2[4], w2, hp.x); FMA2(acc2[5], w2, hp.y);
            FMA2(acc2[6], w3, hp.x); FMA2(acc2[7], w3, hp.y);
        }

        ulonglong2* rp = (ulonglong2*)&red[(s * 32 + lane) * 16];
        rp[0] = make_ulonglong2(acc2[0], acc2[1]);
        rp[1] = make_ulonglong2(acc2[2], acc2[3]);
        rp[2] = make_ulonglong2(acc2[4], acc2[5]);
        rp[3] = make_ulonglong2(acc2[6], acc2[7]);
        __syncthreads();

        if (eact) {
            float gv[4];
#pragma unroll
            for (int g = 0; g < 4; g++) {
                int co  = g * 8 + eu;
                int cg2 = co >> 2, c2 = co & 3;
                float sum = pg[g];
#pragma unroll
                for (int s2 = 0; s2 < 8; s2++)
                    sum += red[(s2 * 32 + ebg * 8 + cg2) * 16 + c2 * 4 + ebi];
                gv[g] = sum;
            }
            float ig = sigf(gv[0]);
            float fg = sigf(gv[1]);
            float gg = tanhf(gv[2]);
            float og = sigf(gv[3]);
            float c  = fg * cT[tid] + ig * gg;
            float hn = og * tanhf(c);
            cT[tid] = c;
            __stcg(&hout[ej * 16 + eb], hn);
            y[erow * ldy + ej] = hn;
            if (t == TSZ - 1) cOut[ej * 16 + eb] = c;
        } else if (epad) {
            y[erow * ldy + ej] = 0.f;
        }
        grid_bar_flags(flags, nCTA, (unsigned)(t + 2));
    }
}

// ---------------- finalize ----------------
__global__ void finalize_k(const float* __restrict__ y1, const float* __restrict__ y2,
                           const float* __restrict__ y3, const float* __restrict__ cT1,
                           const float* __restrict__ cT2, const float* __restrict__ cT3,
                           float* __restrict__ out) {
    int i = blockIdx.x * blockDim.x + threadIdx.x;
    if (i >= 86400) return;
    const size_t O = (size_t)BSZ * VSZ * TSZ;
    if (i < 18400) {
        int b = i / 1150, j = i % 1150;
        out[O + i] = y1[((size_t)b * TSZ + 127) * HPAD + j];
    } else if (i < 36800) {
        int k = i - 18400; int b = k / 1150, j = k % 1150;
        out[O + i] = y2[((size_t)b * TSZ + 127) * HPAD + j];
    } else if (i < 43200) {
        int k = i - 36800; int b = k / 400, j = k % 400;
        out[O + i] = y3[((size_t)b * TSZ + 127) * 400 + j];
    } else if (i < 61600) {
        int k = i - 43200; int j = (k % 1150), b = k / 1150;
        out[O + i] = cT1[j * 16 + b];
    } else if (i < 80000) {
        int k = i - 61600; int j = (k % 1150), b = k / 1150;
        out[O + i] = cT2[j * 16 + b];
    } else {
        int k = i - 80000; int j = (k % 400), b = k / 400;
        out[O + i] = cT3[j * 16 + b];
    }
}

// ---------------- launch ----------------
extern "C" void kernel_launch(void* const* d_in, const int* in_sizes, int n_in,
                              void* d_out, int out_size) {
    const float* emb  = (const float*)d_in[0];
    const float* Wih1 = (const float*)d_in[1];
    const float* Whh1 = (const float*)d_in[2];
    const float* bih1 = (const float*)d_in[3];
    const float* bhh1 = (const float*)d_in[4];
    const float* Wih2 = (const float*)d_in[5];
    const float* Whh2 = (const float*)d_in[6];
    const float* bih2 = (const float*)d_in[7];
    const float* bhh2 = (const float*)d_in[8];
    const float* Wih3 = (const float*)d_in[9];
    const float* Whh3 = (const float*)d_in[10];
    const float* bih3 = (const float*)d_in[11];
    const float* bhh3 = (const float*)d_in[12];
    const float* linb = (const float*)d_in[13];
    const int*   x    = (const int*)d_in[14];
    float* out = (float*)d_out;

    float *y0, *y1, *y2, *y3, *pre, *Wt1, *Wt2, *Wt3, *W2p, *W3p;
    float *hTa, *hTb, *cT1, *cT2, *cT3;
    unsigned* flags;
    cudaGetSymbolAddress((void**)&y0,  g_y0);
    cudaGetSymbolAddress((void**)&y1,  g_y1);
    cudaGetSymbolAddress((void**)&y2,  g_y2);
    cudaGetSymbolAddress((void**)&y3,  g_y3);
    cudaGetSymbolAddress((void**)&pre, g_pre);
    cudaGetSymbolAddress((void**)&Wt1, g_Wt1);
    cudaGetSymbolAddress((void**)&Wt2, g_Wt2);
    cudaGetSymbolAddress((void**)&Wt3, g_Wt3);
    cudaGetSymbolAddress((void**)&W2p, g_Wih2p);
    cudaGetSymbolAddress((void**)&W3p, g_Wih3p);
    cudaGetSymbolAddress((void**)&hTa, g_hTa);
    cudaGetSymbolAddress((void**)&hTb, g_hTb);
    cudaGetSymbolAddress((void**)&cT1, g_cT1);
    cudaGetSymbolAddress((void**)&cT2, g_cT2);
    cudaGetSymbolAddress((void**)&cT3, g_cT3);
    cudaGetSymbolAddress((void**)&flags, g_flags);

    const int M = TSZ * BSZ;  // 2048
    const int SMEM12 = (HSZ * 32 + 4096 + 128) * 4;  // 164096 B
    const int SMEM3  = (ESZ * 32 + 4096 + 128) * 4;  //  68096 B
    static int smem_set = 0;
    if (!smem_set) {
        cudaFuncSetAttribute(lstm_layer_k, cudaFuncAttributeMaxDynamicSharedMemorySize, SMEM12);
        smem_set = 1;
    }

    // ----- layer 1: embed (zeros flags) -> wtrans1 -> gemm1 -> lstm1 (4th launch: profiled)
    embed_k<<<(TSZ * BSZ * ESZ + 255) / 256, 256>>>(emb, x, y0, flags);
    wtrans_k<<<dim3(GP12 / 32, (HSZ + 31) / 32), dim3(32, 8)>>>(Whh1, Wt1, HSZ, GP12);
    gemm_tc<<<dim3((4 * HSZ + 127) / 128, M / 128), 256>>>(y0, Wih1, bih1, bhh1, pre,
                                                           M, 4 * HSZ, ESZ, 0);
    lstm_layer_k<<<GP12 / 32, 256, SMEM12>>>(pre, Wt1, hTa, hTb, cT1, y1,
                                             HSZ, GP12, HPAD, flags + 0 * 144 * FLAGSTRIDE);

    // ----- layer 2 -----
    pad_k<<<(4 * HSZ * HPAD + 255) / 256, 256>>>(Wih2, W2p, 4 * HSZ, HSZ, HPAD);
    wtrans_k<<<dim3(GP12 / 32, (HSZ + 31) / 32), dim3(32, 8)>>>(Whh2, Wt2, HSZ, GP12);
    gemm_tc<<<dim3((4 * HSZ + 127) / 128, M / 128), 256>>>(y1, W2p, bih2, bhh2, pre,
                                                           M, 4 * HSZ, HPAD, 0);
    lstm_layer_k<<<GP12 / 32, 256, SMEM12>>>(pre, Wt2, hTa, hTb, cT2, y2,
                                             HSZ, GP12, HPAD, flags + 1 * 144 * FLAGSTRIDE);

    // ----- layer 3 -----
    pad_k<<<(4 * ESZ * HPAD + 255) / 256, 256>>>(Wih3, W3p, 4 * ESZ, HSZ, HPAD);
    wtrans_k<<<dim3(GP3 / 32, (ESZ + 31) / 32), dim3(32, 8)>>>(Whh3, Wt3, ESZ, GP3);
    gemm_tc<<<dim3((4 * ESZ + 127) / 128, M / 128), 256>>>(y2, W3p, bih3, bhh3, pre,
                                                           M, 4 * ESZ, HPAD, 0);
    lstm_layer_k<<<GP3 / 32, 256, SMEM3>>>(pre, Wt3, hTa, hTb, cT3, y3,
                                           ESZ, GP3, ESZ, flags + 2 * 144 * FLAGSTRIDE);

    // ----- tied output projection into (B,V,T) -----
    gemm_tc<<<dim3(VSZ / 128, M / 128), 256>>>(y3, emb, linb, nullptr, out,
                                               M, VSZ, ESZ, 1);

    // ----- final states -----
    finalize_k<<<(86400 + 255) / 256, 256>>>(y1, y2, y3, cT1, cT2, cT3, out);
}

// round 8
// speedup vs baseline: 1.3704x; 1.1220x over previous
#include <cuda_runtime.h>
#include <math.h>

#define VSZ 32000
#define ESZ 400
#define HSZ 1150
#define HPAD 1152
#define BSZ 16
#define TSZ 128
#define GP12 4608
#define GP3  1600
#define FLAGSTRIDE 32   // 128B per CTA flag line
#define NSL 16          // k-slices per CTA (16 warps, 512 threads)

// ---------------- scratch ----------------
__device__ float g_y0[TSZ*BSZ*ESZ];
__device__ float g_y1[TSZ*BSZ*HPAD];
__device__ float g_y2[TSZ*BSZ*HPAD];
__device__ float g_y3[TSZ*BSZ*ESZ];
__device__ float g_pre[TSZ*BSZ*4*HSZ];
__device__ float g_Wt1[HSZ*GP12];
__device__ float g_Wt2[HSZ*GP12];
__device__ float g_Wt3[ESZ*GP3];
__device__ float g_Wih2p[4*HSZ*HPAD];
__device__ float g_Wih3p[4*ESZ*HPAD];
__device__ float g_hTa[HSZ*BSZ];
__device__ float g_hTb[HSZ*BSZ];
__device__ float g_cT1[HSZ*BSZ];
__device__ float g_cT2[HSZ*BSZ];
__device__ float g_cT3[ESZ*BSZ];
__device__ unsigned g_flags[3 * 144 * FLAGSTRIDE];

// ---------------- tiny utility kernels ----------------
__global__ void pad_k(const float* __restrict__ src, float* __restrict__ dst,
                      int rows, int Kin, int Kout) {
    int idx = blockIdx.x * blockDim.x + threadIdx.x;
    if (idx >= rows * Kout) return;
    int r = idx / Kout, k = idx % Kout;
    dst[idx] = (k < Kin) ? src[(size_t)r * Kin + k] : 0.f;
}

__global__ void embed_k(const float* __restrict__ emb, const int* __restrict__ x,
                        float* __restrict__ y0) {
    int idx = blockIdx.x * blockDim.x + threadIdx.x;
    if (idx >= TSZ * BSZ * ESZ) return;
    int e   = idx % ESZ;
    int row = idx / ESZ;
    y0[idx] = emb[(size_t)x[row] * ESZ + e];
}

__global__ void wtrans_k(const float* __restrict__ W, float* __restrict__ Wt,
                         int Hp, int Gp) {
    __shared__ float tile[32][33];
    int jblk = blockIdx.x;
    int k0   = blockIdx.y * 32;
    for (int rr = 0; rr < 32; rr += 8) {
        int r = rr + threadIdx.y;
        int g = r >> 3, u = r & 7;
        int j = jblk * 8 + u;
        int orow = g * Hp + j;
        int k = k0 + threadIdx.x;
        tile[r][threadIdx.x] = (j < Hp && k < Hp) ? W[(size_t)orow * Hp + k] : 0.f;
    }
    __syncthreads();
    for (int kk = 0; kk < 32; kk += 8) {
        int k = k0 + kk + threadIdx.y;
        if (k < Hp)
            Wt[(size_t)k * Gp + jblk * 32 + threadIdx.x] = tile[threadIdx.x][kk + threadIdx.y];
    }
}

// ---------------- tf32x2 tensor-core GEMM ----------------
__device__ __forceinline__ float tf32_rna(float x) {
    float r;
    asm("cvt.rna.tf32.f32 %0, %1;" : "=f"(r) : "f"(x));
    return r;
}

__device__ __forceinline__ void mma_tf32(float4& d, const float* a, const float* b) {
    asm volatile(
        "mma.sync.aligned.m16n8k8.row.col.f32.tf32.tf32.f32 "
        "{%0,%1,%2,%3}, {%4,%5,%6,%7}, {%8,%9}, {%0,%1,%2,%3};\n"
        : "+f"(d.x), "+f"(d.y), "+f"(d.z), "+f"(d.w)
        : "r"(__float_as_uint(a[0])), "r"(__float_as_uint(a[1])),
          "r"(__float_as_uint(a[2])), "r"(__float_as_uint(a[3])),
          "r"(__float_as_uint(b[0])), "r"(__float_as_uint(b[1])));
}

#define SSTR 20

__global__ __launch_bounds__(256)
void gemm_tc(const float* __restrict__ A, const float* __restrict__ Bm,
             const float* __restrict__ bias1, const float* __restrict__ bias2,
             float* __restrict__ C, int M, int N, int K, int mode) {
    __shared__ float As[2][128 * SSTR];
    __shared__ float Bs[2][128 * SSTR];

    const int tid  = threadIdx.x;
    const int lane = tid & 31;
    const int w    = tid >> 5;
    const int wm   = (w & 1) * 64;
    const int wn   = (w >> 1) * 32;
    const int qr   = lane >> 2;
    const int qc   = lane & 3;

    const int m0 = blockIdx.y * 128;
    const int n0 = blockIdx.x * 128;

    const int lrow = tid >> 1;
    const int lk   = (tid & 1) * 8;

    const float* Aptr = A + (size_t)(m0 + lrow) * K + lk;
    const float* Bptr = Bm + (size_t)(n0 + lrow) * K + lk;
    const bool bvalid = (n0 + lrow) < N;

    float4 acc[4][4];
#pragma unroll
    for (int i = 0; i < 4; i++)
#pragma unroll
        for (int j = 0; j < 4; j++) acc[i][j] = make_float4(0.f, 0.f, 0.f, 0.f);

    for (int k0 = 0; k0 < K; k0 += 16) {
        float4 av0 = *(const float4*)(Aptr + k0);
        float4 av1 = *(const float4*)(Aptr + k0 + 4);
        float4 bv0 = bvalid ? *(const float4*)(Bptr + k0) : make_float4(0.f, 0.f, 0.f, 0.f);
        float4 bv1 = bvalid ? *(const float4*)(Bptr + k0 + 4) : make_float4(0.f, 0.f, 0.f, 0.f);
        __syncthreads();
        {
            float va[8] = {av0.x, av0.y, av0.z, av0.w, av1.x, av1.y, av1.z, av1.w};
            float vb[8] = {bv0.x, bv0.y, bv0.z, bv0.w, bv1.x, bv1.y, bv1.z, bv1.w};
            int base = lrow * SSTR + lk;
#pragma unroll
            for (int j = 0; j < 8; j++) {
                float hi = tf32_rna(va[j]);
                As[0][base + j] = hi;
                As[1][base + j] = tf32_rna(va[j] - hi);
                float bhi = tf32_rna(vb[j]);
                Bs[0][base + j] = bhi;
                Bs[1][base + j] = tf32_rna(vb[j] - bhi);
            }
        }
        __syncthreads();

#pragma unroll
        for (int kk = 0; kk < 16; kk += 8) {
            float ah[4][4], al[4][4], bh[4][2], bl[4][2];
#pragma unroll
            for (int mt = 0; mt < 4; mt++) {
                int base = (wm + mt * 16 + qr) * SSTR + kk + qc;
                ah[mt][0] = As[0][base];
                ah[mt][1] = As[0][base + 8 * SSTR];
                ah[mt][2] = As[0][base + 4];
                ah[mt][3] = As[0][base + 8 * SSTR + 4];
                al[mt][0] = As[1][base];
                al[mt][1] = As[1][base + 8 * SSTR];
                al[mt][2] = As[1][base + 4];
                al[mt][3] = As[1][base + 8 * SSTR + 4];
            }
#pragma unroll
            for (int nt = 0; nt < 4; nt++) {
                int base = (wn + nt * 8 + qr) * SSTR + kk + qc;
                bh[nt][0] = Bs[0][base];
                bh[nt][1] = Bs[0][base + 4];
                bl[nt][0] = Bs[1][base];
                bl[nt][1] = Bs[1][base + 4];
            }
#pragma unroll
            for (int mt = 0; mt < 4; mt++)
#pragma unroll
                for (int nt = 0; nt < 4; nt++) {
                    mma_tf32(acc[mt][nt], ah[mt], bh[nt]);
                    mma_tf32(acc[mt][nt], ah[mt], bl[nt]);
                    mma_tf32(acc[mt][nt], al[mt], bh[nt]);
                }
        }
    }

#pragma unroll
    for (int mt = 0; mt < 4; mt++) {
        int mrow = m0 + wm + mt * 16 + qr;
#pragma unroll
        for (int nt = 0; nt < 4; nt++) {
            int n = n0 + wn + nt * 8 + 2 * qc;
            if (n >= N) continue;
            float b0 = 0.f, b1 = 0.f;
            if (bias1) { b0 += bias1[n]; b1 += bias1[n + 1]; }
            if (bias2) { b0 += bias2[n]; b1 += bias2[n + 1]; }
            float4 v = acc[mt][nt];
            if (mode == 0) {
                C[(size_t)mrow * N + n]           = v.x + b0;
                C[(size_t)mrow * N + n + 1]       = v.y + b1;
                C[(size_t)(mrow + 8) * N + n]     = v.z + b0;
                C[(size_t)(mrow + 8) * N + n + 1] = v.w + b1;
            } else {
                int bidx = m0 >> 7;
                int t = (mrow - m0);
                size_t base = ((size_t)bidx * N + n) * TSZ + t;
                C[base]           = v.x + b0;
                C[base + TSZ]     = v.y + b1;
                C[base + 8]       = v.z + b0;
                C[base + TSZ + 8] = v.w + b1;
            }
        }
    }
}

// ---------------- persistent LSTM layer kernel (512 threads, 16 k-slices) ----------------
__device__ __forceinline__ float sigf(float z) { return 1.f / (1.f + expf(-z)); }

#define FMA2(d, a, b) \
    asm("fma.rn.f32x2 %0, %1, %2, %0;" : "+l"(d) : "l"(a), "l"(b))

// replay-safe distributed flag barrier: phases are relative to the flag value
// observed at kernel entry (base), so isolated ncu replays still synchronize.
__device__ __forceinline__ void grid_bar_flags(unsigned* flags, int nCTA, unsigned target) {
    __syncthreads();
    if (threadIdx.x == 0) {
        asm volatile("st.release.gpu.global.u32 [%0], %1;"
                     :: "l"(flags + (size_t)blockIdx.x * FLAGSTRIDE), "r"(target) : "memory");
    }
    if (threadIdx.x < nCTA) {
        unsigned v;
        do {
            asm volatile("ld.acquire.gpu.global.u32 %0, [%1];"
                         : "=r"(v) : "l"(flags + (size_t)threadIdx.x * FLAGSTRIDE) : "memory");
        } while ((int)(v - target) < 0);
    }
    __syncthreads();
}

__global__ __launch_bounds__(512, 1)
void lstm_layer_k(const float* __restrict__ pre, const float* __restrict__ Wt,
                  float* __restrict__ hA, float* __restrict__ hB,
                  float* __restrict__ cOut, float* __restrict__ y,
                  int Hp, int Gp, int ldy, unsigned* flags) {
    extern __shared__ float sm[];
    float* sW   = sm;                       // Hp*32
    float* red  = sm + Hp * 32;             // NSL*32*16 = 8192
    float* gsum = red + NSL * 32 * 16;      // 512
    float* cT   = gsum + 512;               // 128
    unsigned* sbase = (unsigned*)(cT + 128);

    const int tid  = threadIdx.x;
    const int jblk = blockIdx.x;
    const int nCTA = gridDim.x;
    const int lane = tid & 31;
    const int s    = tid >> 5;       // k-slice 0..15
    const int bg   = lane >> 3;      // batch group 0..3
    const int cg   = lane & 7;       // col group 0..7
    const int G4 = 4 * Hp;

    // phase-1 epilogue mapping (all 512 threads: one (output, gate) pair each)
    const int p_out = tid >> 2;          // 0..127
    const int p_g   = tid & 3;           // gate
    const int p_eb  = p_out & 15;
    const int p_eu  = p_out >> 4;
    const int p_ej  = jblk * 8 + p_eu;
    const bool p_act = p_ej < Hp;
    const int p_ebg = p_eb >> 2, p_ebi = p_eb & 3;
    const int p_co  = p_g * 8 + p_eu;
    const int p_cg2 = p_co >> 2, p_c2 = p_co & 3;

    // phase-2 mapping (tid<128)
    const int eb = tid & 15;
    const int eu = tid >> 4;
    const int ej = jblk * 8 + eu;
    const bool eact = (tid < 128) && (ej < Hp);
    const bool epad = (tid < 128) && (ej >= Hp) && (ej < ldy);

    // read this CTA's flag base (replay-safe barrier)
    if (tid == 0) *sbase = flags[(size_t)jblk * FLAGSTRIDE];
    for (int idx = tid; idx < Hp * 32; idx += 512) {
        int k = idx >> 5, rr = idx & 31;
        sW[idx] = Wt[(size_t)k * Gp + jblk * 32 + rr];
    }
    if (tid < 128) {
        cT[tid] = 0.f;
        if (ej < Hp) hA[ej * 16 + eb] = 0.f;
    }
    __syncthreads();
    const unsigned base = *sbase;
    grid_bar_flags(flags, nCTA, base + 1u);

    const float4* sW4base = (const float4*)sW;

    for (int t = 0; t < TSZ; t++) {
        const float* hin = (t & 1) ? hB : hA;
        float* hout      = (t & 1) ? hA : hB;

        // prefetch this thread's pre-activation value (1 per thread)
        float pg1 = 0.f;
        if (p_act)
            pg1 = __ldcg(pre + ((size_t)p_eb * TSZ + t) * G4 + (size_t)p_g * Hp + p_ej);

        unsigned long long acc2[8];
#pragma unroll
        for (int i = 0; i < 8; i++) acc2[i] = 0ULL;

        const ulonglong2* hv = (const ulonglong2*)hin;
#pragma unroll 4
        for (int k = s; k < Hp; k += NSL) {
            float4 wq = sW4base[k * 8 + cg];
            ulonglong2 hp = hv[k * 4 + bg];
            unsigned long long w0, w1, w2, w3;
            asm("mov.b64 %0, {%1, %1};" : "=l"(w0) : "r"(__float_as_uint(wq.x)));
            asm("mov.b64 %0, {%1, %1};" : "=l"(w1) : "r"(__float_as_uint(wq.y)));
            asm("mov.b64 %0, {%1, %1};" : "=l"(w2) : "r"(__float_as_uint(wq.z)));
            asm("mov.b64 %0, {%1, %1};" : "=l"(w3) : "r"(__float_as_uint(wq.w)));
            FMA2(acc2[0], w0, hp.x); FMA2(acc2[1], w0, hp.y);
            FMA2(acc2[2], w1, hp.x); FMA2(acc2[3], w1, hp.y);
            FMA2(acc2[4], w2, hp.x); FMA2(acc2[5], w2, hp.y);
            FMA2(acc2[6], w3, hp.x); FMA2(acc2[7], w3, hp.y);
        }

        ulonglong2* rp = (ulonglong2*)&red[(s * 32 + lane) * 16];
        rp[0] = make_ulonglong2(acc2[0], acc2[1]);
        rp[1] = make_ulonglong2(acc2[2], acc2[3]);
        rp[2] = make_ulonglong2(acc2[4], acc2[5]);
        rp[3] = make_ulonglong2(acc2[6], acc2[7]);
        __syncthreads();

        // phase 1: each thread reduces one (output, gate) over 16 slices
        {
            float sum = pg1;
            int ridx = (p_ebg * 8 + p_cg2) * 16 + p_c2 * 4 + p_ebi;
#pragma unroll
            for (int s2 = 0; s2 < NSL; s2++)
                sum += red[s2 * 512 + ridx];
            gsum[tid] = sum;
        }
        __syncthreads();

        // phase 2: pointwise cell update
        if (eact) {
            float4 gv = *(const float4*)&gsum[tid * 4];
            float ig = sigf(gv.x);
            float fg = sigf(gv.y);
            float gg = tanhf(gv.z);
            float og = sigf(gv.w);
            float c  = fg * cT[tid] + ig * gg;
            float hn = og * tanhf(c);
            cT[tid] = c;
            __stcg(&hout[ej * 16 + eb], hn);
            y[((size_t)eb * TSZ + t) * ldy + ej] = hn;
            if (t == TSZ - 1) cOut[ej * 16 + eb] = c;
        } else if (epad) {
            y[((size_t)eb * TSZ + t) * ldy + ej] = 0.f;
        }
        grid_bar_flags(flags, nCTA, base + (unsigned)(t + 2));
    }
}

// ---------------- finalize ----------------
__global__ void finalize_k(const float* __restrict__ y1, const float* __restrict__ y2,
                           const float* __restrict__ y3, const float* __restrict__ cT1,
                           const float* __restrict__ cT2, const float* __restrict__ cT3,
                           float* __restrict__ out) {
    int i = blockIdx.x * blockDim.x + threadIdx.x;
    if (i >= 86400) return;
    const size_t O = (size_t)BSZ * VSZ * TSZ;
    if (i < 18400) {
        int b = i / 1150, j = i % 1150;
        out[O + i] = y1[((size_t)b * TSZ + 127) * HPAD + j];
    } else if (i < 36800) {
        int k = i - 18400; int b = k / 1150, j = k % 1150;
        out[O + i] = y2[((size_t)b * TSZ + 127) * HPAD + j];
    } else if (i < 43200) {
        int k = i - 36800; int b = k / 400, j = k % 400;
        out[O + i] = y3[((size_t)b * TSZ + 127) * 400 + j];
    } else if (i < 61600) {
        int k = i - 43200; int j = (k % 1150), b = k / 1150;
        out[O + i] = cT1[j * 16 + b];
    } else if (i < 80000) {
        int k = i - 61600; int j = (k % 1150), b = k / 1150;
        out[O + i] = cT2[j * 16 + b];
    } else {
        int k = i - 80000; int j = (k % 400), b = k / 400;
        out[O + i] = cT3[j * 16 + b];
    }
}

// ---------------- launch ----------------
extern "C" void kernel_launch(void* const* d_in, const int* in_sizes, int n_in,
                              void* d_out, int out_size) {
    const float* emb  = (const float*)d_in[0];
    const float* Wih1 = (const float*)d_in[1];
    const float* Whh1 = (const float*)d_in[2];
    const float* bih1 = (const float*)d_in[3];
    const float* bhh1 = (const float*)d_in[4];
    const float* Wih2 = (const float*)d_in[5];
    const float* Whh2 = (const float*)d_in[6];
    const float* bih2 = (const float*)d_in[7];
    const float* bhh2 = (const float*)d_in[8];
    const float* Wih3 = (const float*)d_in[9];
    const float* Whh3 = (const float*)d_in[10];
    const float* bih3 = (const float*)d_in[11];
    const float* bhh3 = (const float*)d_in[12];
    const float* linb = (const float*)d_in[13];
    const int*   x    = (const int*)d_in[14];
    float* out = (float*)d_out;

    float *y0, *y1, *y2, *y3, *pre, *Wt1, *Wt2, *Wt3, *W2p, *W3p;
    float *hTa, *hTb, *cT1, *cT2, *cT3;
    unsigned* flags;
    cudaGetSymbolAddress((void**)&y0,  g_y0);
    cudaGetSymbolAddress((void**)&y1,  g_y1);
    cudaGetSymbolAddress((void**)&y2,  g_y2);
    cudaGetSymbolAddress((void**)&y3,  g_y3);
    cudaGetSymbolAddress((void**)&pre, g_pre);
    cudaGetSymbolAddress((void**)&Wt1, g_Wt1);
    cudaGetSymbolAddress((void**)&Wt2, g_Wt2);
    cudaGetSymbolAddress((void**)&Wt3, g_Wt3);
    cudaGetSymbolAddress((void**)&W2p, g_Wih2p);
    cudaGetSymbolAddress((void**)&W3p, g_Wih3p);
    cudaGetSymbolAddress((void**)&hTa, g_hTa);
    cudaGetSymbolAddress((void**)&hTb, g_hTb);
    cudaGetSymbolAddress((void**)&cT1, g_cT1);
    cudaGetSymbolAddress((void**)&cT2, g_cT2);
    cudaGetSymbolAddress((void**)&cT3, g_cT3);
    cudaGetSymbolAddress((void**)&flags, g_flags);

    const int M = TSZ * BSZ;  // 2048
    const int SMEM12 = (HSZ * 32 + NSL * 32 * 16 + 512 + 128 + 32) * 4;
    const int SMEM3  = (ESZ * 32 + NSL * 32 * 16 + 512 + 128 + 32) * 4;
    static int smem_set = 0;
    if (!smem_set) {
        cudaFuncSetAttribute(lstm_layer_k, cudaFuncAttributeMaxDynamicSharedMemorySize, SMEM12);
        smem_set = 1;
    }

    // ----- layer 1: embed -> wtrans1 -> gemm1 -> lstm1 (4th launch: profiled)
    embed_k<<<(TSZ * BSZ * ESZ + 255) / 256, 256>>>(emb, x, y0);
    wtrans_k<<<dim3(GP12 / 32, (HSZ + 31) / 32), dim3(32, 8)>>>(Whh1, Wt1, HSZ, GP12);
    gemm_tc<<<dim3((4 * HSZ + 127) / 128, M / 128), 256>>>(y0, Wih1, bih1, bhh1, pre,
                                                           M, 4 * HSZ, ESZ, 0);
    lstm_layer_k<<<GP12 / 32, 512, SMEM12>>>(pre, Wt1, hTa, hTb, cT1, y1,
                                             HSZ, GP12, HPAD, flags + 0 * 144 * FLAGSTRIDE);

    // ----- layer 2 -----
    pad_k<<<(4 * HSZ * HPAD + 255) / 256, 256>>>(Wih2, W2p, 4 * HSZ, HSZ, HPAD);
    wtrans_k<<<dim3(GP12 / 32, (HSZ + 31) / 32), dim3(32, 8)>>>(Whh2, Wt2, HSZ, GP12);
    gemm_tc<<<dim3((4 * HSZ + 127) / 128, M / 128), 256>>>(y1, W2p, bih2, bhh2, pre,
                                                           M, 4 * HSZ, HPAD, 0);
    lstm_layer_k<<<GP12 / 32, 512, SMEM12>>>(pre, Wt2, hTa, hTb, cT2, y2,
                                             HSZ, GP12, HPAD, flags + 1 * 144 * FLAGSTRIDE);

    // ----- layer 3 -----
    pad_k<<<(4 * ESZ * HPAD + 255) / 256, 256>>>(Wih3, W3p, 4 * ESZ, HSZ, HPAD);
    wtrans_k<<<dim3(GP3 / 32, (ESZ + 31) / 32), dim3(32, 8)>>>(Whh3, Wt3, ESZ, GP3);
    gemm_tc<<<dim3((4 * ESZ + 127) / 128, M / 128), 256>>>(y2, W3p, bih3, bhh3, pre,
                                                           M, 4 * ESZ, HPAD, 0);
    lstm_layer_k<<<GP3 / 32, 512, SMEM3>>>(pre, Wt3, hTa, hTb, cT3, y3,
                                           ESZ, GP3, ESZ, flags + 2 * 144 * FLAGSTRIDE);

    // ----- tied output projection into (B,V,T) -----
    gemm_tc<<<dim3(VSZ / 128, M / 128), 256>>>(y3, emb, linb, nullptr, out,
                                               M, VSZ, ESZ, 1);

    // ----- final states -----
    finalize_k<<<(86400 + 255) / 256, 256>>>(y1, y2, y3, cT1, cT2, cT3, out);
}

// round 9
// speedup vs baseline: 1.4490x; 1.0574x over previous
#include <cuda_runtime.h>
#include <math.h>

#define VSZ 32000
#define ESZ 400
#define HSZ 1150
#define HPAD 1152
#define BSZ 16
#define TSZ 128
#define GP12 4608
#define GP3  1600
#define FLAGSTRIDE 32
#define NSL 16

// ---------------- scratch ----------------
__device__ float g_y0[TSZ*BSZ*ESZ];
__device__ float g_y1[TSZ*BSZ*HPAD];
__device__ float g_y2[TSZ*BSZ*HPAD];
__device__ float g_y3[TSZ*BSZ*ESZ];
__device__ float g_pre[TSZ*BSZ*4*HSZ];
__device__ float g_Wt1[HSZ*GP12];
__device__ float g_Wt2[HSZ*GP12];
__device__ float g_Wt3[ESZ*GP3];
__device__ float g_Wih2p[4*HSZ*HPAD];
__device__ float g_Wih3p[4*ESZ*HPAD];
__device__ float g_hTa[HSZ*BSZ];
__device__ float g_hTb[HSZ*BSZ];
__device__ float g_cT1[HSZ*BSZ];
__device__ float g_cT2[HSZ*BSZ];
__device__ float g_cT3[ESZ*BSZ];
__device__ unsigned g_flags[3 * 144 * FLAGSTRIDE];

// ---------------- tiny utility kernels ----------------
__global__ void pad_k(const float* __restrict__ src, float* __restrict__ dst,
                      int rows, int Kin, int Kout) {
    int idx = blockIdx.x * blockDim.x + threadIdx.x;
    if (idx >= rows * Kout) return;
    int r = idx / Kout, k = idx % Kout;
    dst[idx] = (k < Kin) ? src[(size_t)r * Kin + k] : 0.f;
}

__global__ void embed_k(const float* __restrict__ emb, const int* __restrict__ x,
                        float* __restrict__ y0) {
    int idx = blockIdx.x * blockDim.x + threadIdx.x;
    if (idx >= TSZ * BSZ * ESZ) return;
    int e   = idx % ESZ;
    int row = idx / ESZ;
    y0[idx] = emb[(size_t)x[row] * ESZ + e];
}

__global__ void wtrans_k(const float* __restrict__ W, float* __restrict__ Wt,
                         int Hp, int Gp) {
    __shared__ float tile[32][33];
    int jblk = blockIdx.x;
    int k0   = blockIdx.y * 32;
    for (int rr = 0; rr < 32; rr += 8) {
        int r = rr + threadIdx.y;
        int g = r >> 3, u = r & 7;
        int j = jblk * 8 + u;
        int orow = g * Hp + j;
        int k = k0 + threadIdx.x;
        tile[r][threadIdx.x] = (j < Hp && k < Hp) ? W[(size_t)orow * Hp + k] : 0.f;
    }
    __syncthreads();
    for (int kk = 0; kk < 32; kk += 8) {
        int k = k0 + kk + threadIdx.y;
        if (k < Hp)
            Wt[(size_t)k * Gp + jblk * 32 + threadIdx.x] = tile[threadIdx.x][kk + threadIdx.y];
    }
}

// ---------------- tf32x2 tensor-core GEMM (BM=256, warp tile 64x64) ----------------
__device__ __forceinline__ float tf32_rna(float x) {
    float r;
    asm("cvt.rna.tf32.f32 %0, %1;" : "=f"(r) : "f"(x));
    return r;
}

__device__ __forceinline__ void mma_tf32(float4& d, const float* a, const float* b) {
    asm volatile(
        "mma.sync.aligned.m16n8k8.row.col.f32.tf32.tf32.f32 "
        "{%0,%1,%2,%3}, {%4,%5,%6,%7}, {%8,%9}, {%0,%1,%2,%3};\n"
        : "+f"(d.x), "+f"(d.y), "+f"(d.z), "+f"(d.w)
        : "r"(__float_as_uint(a[0])), "r"(__float_as_uint(a[1])),
          "r"(__float_as_uint(a[2])), "r"(__float_as_uint(a[3])),
          "r"(__float_as_uint(b[0])), "r"(__float_as_uint(b[1])));
}

#define SSTR 20
#define GEMM_SMEM ((2*256 + 2*128) * SSTR * 4)

// BM=256, BN=128, BK=16, 256 threads (8 warps, grid 4m x 2n), warp tile 64x64.
// mode 0: C[m*N + n];  mode 1: C[((b*N + n)*T) + t], m = b*T + t.
__global__ __launch_bounds__(256, 1)
void gemm_tc(const float* __restrict__ A, const float* __restrict__ Bm,
             const float* __restrict__ bias1, const float* __restrict__ bias2,
             float* __restrict__ C, int M, int N, int K, int mode) {
    extern __shared__ float gsm[];
    float* As0 = gsm;
    float* As1 = gsm + 256 * SSTR;
    float* Bs0 = gsm + 512 * SSTR;
    float* Bs1 = Bs0 + 128 * SSTR;

    const int tid  = threadIdx.x;
    const int lane = tid & 31;
    const int w    = tid >> 5;
    const int wm   = (w >> 1) * 64;   // 0,64,128,192
    const int wn   = (w & 1) * 64;    // 0,64
    const int qr   = lane >> 2;
    const int qc   = lane & 3;

    const int m0 = blockIdx.y * 256;
    const int n0 = blockIdx.x * 128;

    const float* Aptr = A + (size_t)(m0 + tid) * K;
    const int brow = tid >> 1, bk = (tid & 1) * 8;
    const float* Bptr = Bm + (size_t)(n0 + brow) * K + bk;
    const bool bvalid = (n0 + brow) < N;

    float4 acc[4][8];
#pragma unroll
    for (int i = 0; i < 4; i++)
#pragma unroll
        for (int j = 0; j < 8; j++) acc[i][j] = make_float4(0.f, 0.f, 0.f, 0.f);

    // prefetch slab 0
    float4 pa0 = *(const float4*)(Aptr + 0);
    float4 pa1 = *(const float4*)(Aptr + 4);
    float4 pa2 = *(const float4*)(Aptr + 8);
    float4 pa3 = *(const float4*)(Aptr + 12);
    float4 pb0 = bvalid ? *(const float4*)(Bptr + 0) : make_float4(0.f,0.f,0.f,0.f);
    float4 pb1 = bvalid ? *(const float4*)(Bptr + 4) : make_float4(0.f,0.f,0.f,0.f);

    for (int k0 = 0; k0 < K; k0 += 16) {
        __syncthreads();   // previous compute done before smem overwrite
        {
            float va[16] = {pa0.x,pa0.y,pa0.z,pa0.w, pa1.x,pa1.y,pa1.z,pa1.w,
                            pa2.x,pa2.y,pa2.z,pa2.w, pa3.x,pa3.y,pa3.z,pa3.w};
            int abase = tid * SSTR;
#pragma unroll
            for (int j = 0; j < 16; j++) {
                float hi = tf32_rna(va[j]);
                As0[abase + j] = hi;
                As1[abase + j] = tf32_rna(va[j] - hi);
            }
            float vb[8] = {pb0.x,pb0.y,pb0.z,pb0.w, pb1.x,pb1.y,pb1.z,pb1.w};
            int bbase = brow * SSTR + bk;
#pragma unroll
            for (int j = 0; j < 8; j++) {
                float hi = tf32_rna(vb[j]);
                Bs0[bbase + j] = hi;
                Bs1[bbase + j] = tf32_rna(vb[j] - hi);
            }
        }
        __syncthreads();

        if (k0 + 16 < K) {   // prefetch next slab (overlaps compute below)
            pa0 = *(const float4*)(Aptr + k0 + 16);
            pa1 = *(const float4*)(Aptr + k0 + 20);
            pa2 = *(const float4*)(Aptr + k0 + 24);
            pa3 = *(const float4*)(Aptr + k0 + 28);
            pb0 = bvalid ? *(const float4*)(Bptr + k0 + 16) : make_float4(0.f,0.f,0.f,0.f);
            pb1 = bvalid ? *(const float4*)(Bptr + k0 + 20) : make_float4(0.f,0.f,0.f,0.f);
        }

#pragma unroll
        for (int kk = 0; kk < 16; kk += 8) {
            float ah[4][4], al[4][4];
#pragma unroll
            for (int mt = 0; mt < 4; mt++) {
                int base = (wm + mt * 16 + qr) * SSTR + kk + qc;
                ah[mt][0] = As0[base];
                ah[mt][1] = As0[base + 8 * SSTR];
                ah[mt][2] = As0[base + 4];
                ah[mt][3] = As0[base + 8 * SSTR + 4];
                al[mt][0] = As1[base];
                al[mt][1] = As1[base + 8 * SSTR];
                al[mt][2] = As1[base + 4];
                al[mt][3] = As1[base + 8 * SSTR + 4];
            }
#pragma unroll
            for (int ng = 0; ng < 2; ng++) {
                float bh[4][2], bl[4][2];
#pragma unroll
                for (int i = 0; i < 4; i++) {
                    int base = (wn + (ng * 4 + i) * 8 + qr) * SSTR + kk + qc;
                    bh[i][0] = Bs0[base];
                    bh[i][1] = Bs0[base + 4];
                    bl[i][0] = Bs1[base];
                    bl[i][1] = Bs1[base + 4];
                }
#pragma unroll
                for (int mt = 0; mt < 4; mt++)
#pragma unroll
                    for (int i = 0; i < 4; i++) {
                        mma_tf32(acc[mt][ng * 4 + i], ah[mt], bh[i]);
                        mma_tf32(acc[mt][ng * 4 + i], ah[mt], bl[i]);
                        mma_tf32(acc[mt][ng * 4 + i], al[mt], bh[i]);
                    }
            }
        }
    }

    // epilogue
    const int bw = (m0 + wm) >> 7;           // mode1: batch (warp-constant)
    const int tw = (wm & 127);               // mode1: t offset of warp base
#pragma unroll
    for (int mt = 0; mt < 4; mt++) {
        int mrow = m0 + wm + mt * 16 + qr;
#pragma unroll
        for (int nt = 0; nt < 8; nt++) {
            int n = n0 + wn + nt * 8 + 2 * qc;
            if (n >= N) continue;
            float b0 = 0.f, b1 = 0.f;
            if (bias1) { b0 += bias1[n]; b1 += bias1[n + 1]; }
            if (bias2) { b0 += bias2[n]; b1 += bias2[n + 1]; }
            float4 v = acc[mt][nt];
            if (mode == 0) {
                C[(size_t)mrow * N + n]           = v.x + b0;
                C[(size_t)mrow * N + n + 1]       = v.y + b1;
                C[(size_t)(mrow + 8) * N + n]     = v.z + b0;
                C[(size_t)(mrow + 8) * N + n + 1] = v.w + b1;
            } else {
                int t = tw + mt * 16 + qr;
                size_t base = ((size_t)bw * N + n) * TSZ + t;
                C[base]           = v.x + b0;
                C[base + TSZ]     = v.y + b1;
                C[base + 8]       = v.z + b0;
                C[base + TSZ + 8] = v.w + b1;
            }
        }
    }
}

// ---------------- persistent LSTM layer kernel ----------------
__device__ __forceinline__ float sigf(float z) { return 1.f / (1.f + expf(-z)); }

#define FMA2(d, a, b) \
    asm("fma.rn.f32x2 %0, %1, %2, %0;" : "+l"(d) : "l"(a), "l"(b))

__device__ __forceinline__ void grid_bar_flags(unsigned* flags, int nCTA, unsigned target) {
    __syncthreads();
    if (threadIdx.x == 0) {
        asm volatile("st.release.gpu.global.u32 [%0], %1;"
                     :: "l"(flags + (size_t)blockIdx.x * FLAGSTRIDE), "r"(target) : "memory");
    }
    if (threadIdx.x < nCTA) {
        unsigned v;
        do {
            asm volatile("ld.acquire.gpu.global.u32 %0, [%1];"
                         : "=r"(v) : "l"(flags + (size_t)threadIdx.x * FLAGSTRIDE) : "memory");
        } while ((int)(v - target) < 0);
    }
    __syncthreads();
}

__global__ __launch_bounds__(512, 1)
void lstm_layer_k(const float* __restrict__ pre, const float* __restrict__ Wt,
                  float* __restrict__ hA, float* __restrict__ hB,
                  float* __restrict__ cOut, float* __restrict__ y,
                  int Hp, int Gp, int ldy, unsigned* flags) {
    extern __shared__ float sm[];
    float* sW   = sm;
    float* red  = sm + Hp * 32;
    float* gsum = red + NSL * 32 * 16;
    float* cT   = gsum + 512;
    unsigned* sbase = (unsigned*)(cT + 128);

    const int tid  = threadIdx.x;
    const int jblk = blockIdx.x;
    const int nCTA = gridDim.x;
    const int lane = tid & 31;
    const int s    = tid >> 5;
    const int bg   = lane >> 3;
    const int cg   = lane & 7;
    const int G4 = 4 * Hp;

    const int p_out = tid >> 2;
    const int p_g   = tid & 3;
    const int p_eb  = p_out & 15;
    const int p_eu  = p_out >> 4;
    const int p_ej  = jblk * 8 + p_eu;
    const bool p_act = p_ej < Hp;
    const int p_ebg = p_eb >> 2, p_ebi = p_eb & 3;
    const int p_co  = p_g * 8 + p_eu;
    const int p_cg2 = p_co >> 2, p_c2 = p_co & 3;

    const int eb = tid & 15;
    const int eu = tid >> 4;
    const int ej = jblk * 8 + eu;
    const bool eact = (tid < 128) && (ej < Hp);
    const bool epad = (tid < 128) && (ej >= Hp) && (ej < ldy);

    if (tid == 0) *sbase = flags[(size_t)jblk * FLAGSTRIDE];
    for (int idx = tid; idx < Hp * 32; idx += 512) {
        int k = idx >> 5, rr = idx & 31;
        sW[idx] = Wt[(size_t)k * Gp + jblk * 32 + rr];
    }
    if (tid < 128) {
        cT[tid] = 0.f;
        if (ej < Hp) hA[ej * 16 + eb] = 0.f;
    }
    __syncthreads();
    const unsigned base = *sbase;
    grid_bar_flags(flags, nCTA, base + 1u);

    const float4* sW4base = (const float4*)sW;

    for (int t = 0; t < TSZ; t++) {
        const float* hin = (t & 1) ? hB : hA;
        float* hout      = (t & 1) ? hA : hB;

        float pg1 = 0.f;
        if (p_act)
            pg1 = __ldcg(pre + ((size_t)p_eb * TSZ + t) * G4 + (size_t)p_g * Hp + p_ej);

        unsigned long long acc2[8];
#pragma unroll
        for (int i = 0; i < 8; i++) acc2[i] = 0ULL;

        const ulonglong2* hv = (const ulonglong2*)hin;
#pragma unroll 8
        for (int k = s; k < Hp; k += NSL) {
            float4 wq = sW4base[k * 8 + cg];
            ulonglong2 hp = hv[k * 4 + bg];
            unsigned long long w0, w1, w2, w3;
            asm("mov.b64 %0, {%1, %1};" : "=l"(w0) : "r"(__float_as_uint(wq.x)));
            asm("mov.b64 %0, {%1, %1};" : "=l"(w1) : "r"(__float_as_uint(wq.y)));
            asm("mov.b64 %0, {%1, %1};" : "=l"(w2) : "r"(__float_as_uint(wq.z)));
            asm("mov.b64 %0, {%1, %1};" : "=l"(w3) : "r"(__float_as_uint(wq.w)));
            FMA2(acc2[0], w0, hp.x); FMA2(acc2[1], w0, hp.y);
            FMA2(acc2[2], w1, hp.x); FMA2(acc2[3], w1, hp.y);
            FMA2(acc2[4], w2, hp.x); FMA2(acc2[5], w2, hp.y);
            FMA2(acc2[6], w3, hp.x); FMA2(acc2[7], w3, hp.y);
        }

        ulonglong2* rp = (ulonglong2*)&red[(s * 32 + lane) * 16];
        rp[0] = make_ulonglong2(acc2[0], acc2[1]);
        rp[1] = make_ulonglong2(acc2[2], acc2[3]);
        rp[2] = make_ulonglong2(acc2[4], acc2[5]);
        rp[3] = make_ulonglong2(acc2[6], acc2[7]);
        __syncthreads();

        {
            float sum = pg1;
            int ridx = (p_ebg * 8 + p_cg2) * 16 + p_c2 * 4 + p_ebi;
#pragma unroll
            for (int s2 = 0; s2 < NSL; s2++)
                sum += red[s2 * 512 + ridx];
            gsum[tid] = sum;
        }
        __syncthreads();

        if (eact) {
            float4 gv = *(const float4*)&gsum[tid * 4];
            float ig = sigf(gv.x);
            float fg = sigf(gv.y);
            float gg = tanhf(gv.z);
            float og = sigf(gv.w);
            float c  = fg * cT[tid] + ig * gg;
            float hn = og * tanhf(c);
            cT[tid] = c;
            __stcg(&hout[ej * 16 + eb], hn);
            y[((size_t)eb * TSZ + t) * ldy + ej] = hn;
            if (t == TSZ - 1) cOut[ej * 16 + eb] = c;
        } else if (epad) {
            y[((size_t)eb * TSZ + t) * ldy + ej] = 0.f;
        }
        grid_bar_flags(flags, nCTA, base + (unsigned)(t + 2));
    }
}

// ---------------- finalize ----------------
__global__ void finalize_k(const float* __restrict__ y1, const float* __restrict__ y2,
                           const float* __restrict__ y3, const float* __restrict__ cT1,
                           const float* __restrict__ cT2, const float* __restrict__ cT3,
                           float* __restrict__ out) {
    int i = blockIdx.x * blockDim.x + threadIdx.x;
    if (i >= 86400) return;
    const size_t O = (size_t)BSZ * VSZ * TSZ;
    if (i < 18400) {
        int b = i / 1150, j = i % 1150;
        out[O + i] = y1[((size_t)b * TSZ + 127) * HPAD + j];
    } else if (i < 36800) {
        int k = i - 18400; int b = k / 1150, j = k % 1150;
        out[O + i] = y2[((size_t)b * TSZ + 127) * HPAD + j];
    } else if (i < 43200) {
        int k = i - 36800; int b = k / 400, j = k % 400;
        out[O + i] = y3[((size_t)b * TSZ + 127) * 400 + j];
    } else if (i < 61600) {
        int k = i - 43200; int j = (k % 1150), b = k / 1150;
        out[O + i] = cT1[j * 16 + b];
    } else if (i < 80000) {
        int k = i - 61600; int j = (k % 1150), b = k / 1150;
        out[O + i] = cT2[j * 16 + b];
    } else {
        int k = i - 80000; int j = (k % 400), b = k / 400;
        out[O + i] = cT3[j * 16 + b];
    }
}

// ---------------- launch ----------------
extern "C" void kernel_launch(void* const* d_in, const int* in_sizes, int n_in,
                              void* d_out, int out_size) {
    const float* emb  = (const float*)d_in[0];
    const float* Wih1 = (const float*)d_in[1];
    const float* Whh1 = (const float*)d_in[2];
    const float* bih1 = (const float*)d_in[3];
    const float* bhh1 = (const float*)d_in[4];
    const float* Wih2 = (const float*)d_in[5];
    const float* Whh2 = (const float*)d_in[6];
    const float* bih2 = (const float*)d_in[7];
    const float* bhh2 = (const float*)d_in[8];
    const float* Wih3 = (const float*)d_in[9];
    const float* Whh3 = (const float*)d_in[10];
    const float* bih3 = (const float*)d_in[11];
    const float* bhh3 = (const float*)d_in[12];
    const float* linb = (const float*)d_in[13];
    const int*   x    = (const int*)d_in[14];
    float* out = (float*)d_out;

    float *y0, *y1, *y2, *y3, *pre, *Wt1, *Wt2, *Wt3, *W2p, *W3p;
    float *hTa, *hTb, *cT1, *cT2, *cT3;
    unsigned* flags;
    cudaGetSymbolAddress((void**)&y0,  g_y0);
    cudaGetSymbolAddress((void**)&y1,  g_y1);
    cudaGetSymbolAddress((void**)&y2,  g_y2);
    cudaGetSymbolAddress((void**)&y3,  g_y3);
    cudaGetSymbolAddress((void**)&pre, g_pre);
    cudaGetSymbolAddress((void**)&Wt1, g_Wt1);
    cudaGetSymbolAddress((void**)&Wt2, g_Wt2);
    cudaGetSymbolAddress((void**)&Wt3, g_Wt3);
    cudaGetSymbolAddress((void**)&W2p, g_Wih2p);
    cudaGetSymbolAddress((void**)&W3p, g_Wih3p);
    cudaGetSymbolAddress((void**)&hTa, g_hTa);
    cudaGetSymbolAddress((void**)&hTb, g_hTb);
    cudaGetSymbolAddress((void**)&cT1, g_cT1);
    cudaGetSymbolAddress((void**)&cT2, g_cT2);
    cudaGetSymbolAddress((void**)&cT3, g_cT3);
    cudaGetSymbolAddress((void**)&flags, g_flags);

    const int M = TSZ * BSZ;  // 2048
    const int SMEM12 = (HSZ * 32 + NSL * 32 * 16 + 512 + 128 + 32) * 4;
    const int SMEM3  = (ESZ * 32 + NSL * 32 * 16 + 512 + 128 + 32) * 4;
    static int smem_set = 0;
    if (!smem_set) {
        cudaFuncSetAttribute(lstm_layer_k, cudaFuncAttributeMaxDynamicSharedMemorySize, SMEM12);
        cudaFuncSetAttribute(gemm_tc, cudaFuncAttributeMaxDynamicSharedMemorySize, GEMM_SMEM);
        smem_set = 1;
    }

    // ----- layer 1: embed -> wtrans1 -> gemm1 -> lstm1 (4th launch: profiled)
    embed_k<<<(TSZ * BSZ * ESZ + 255) / 256, 256>>>(emb, x, y0);
    wtrans_k<<<dim3(GP12 / 32, (HSZ + 31) / 32), dim3(32, 8)>>>(Whh1, Wt1, HSZ, GP12);
    gemm_tc<<<dim3((4 * HSZ + 127) / 128, M / 256), 256, GEMM_SMEM>>>(
        y0, Wih1, bih1, bhh1, pre, M, 4 * HSZ, ESZ, 0);
    lstm_layer_k<<<GP12 / 32, 512, SMEM12>>>(pre, Wt1, hTa, hTb, cT1, y1,
                                             HSZ, GP12, HPAD, flags + 0 * 144 * FLAGSTRIDE);

    // ----- layer 2 -----
    pad_k<<<(4 * HSZ * HPAD + 255) / 256, 256>>>(Wih2, W2p, 4 * HSZ, HSZ, HPAD);
    wtrans_k<<<dim3(GP12 / 32, (HSZ + 31) / 32), dim3(32, 8)>>>(Whh2, Wt2, HSZ, GP12);
    gemm_tc<<<dim3((4 * HSZ + 127) / 128, M / 256), 256, GEMM_SMEM>>>(
        y1, W2p, bih2, bhh2, pre, M, 4 * HSZ, HPAD, 0);
    lstm_layer_k<<<GP12 / 32, 512, SMEM12>>>(pre, Wt2, hTa, hTb, cT2, y2,
                                             HSZ, GP12, HPAD, flags + 1 * 144 * FLAGSTRIDE);

    // ----- layer 3 -----
    pad_k<<<(4 * ESZ * HPAD + 255) / 256, 256>>>(Wih3, W3p, 4 * ESZ, HSZ, HPAD);
    wtrans_k<<<dim3(GP3 / 32, (ESZ + 31) / 32), dim3(32, 8)>>>(Whh3, Wt3, ESZ, GP3);
    gemm_tc<<<dim3((4 * ESZ + 127) / 128, M / 256), 256, GEMM_SMEM>>>(
        y2, W3p, bih3, bhh3, pre, M, 4 * ESZ, HPAD, 0);
    lstm_layer_k<<<GP3 / 32, 512, SMEM3>>>(pre, Wt3, hTa, hTb, cT3, y3,
                                           ESZ, GP3, ESZ, flags + 2 * 144 * FLAGSTRIDE);

    // ----- tied output projection into (B,V,T) -----
    gemm_tc<<<dim3(VSZ / 128, M / 256), 256, GEMM_SMEM>>>(
        y3, emb, linb, nullptr, out, M, VSZ, ESZ, 1);

    // ----- final states -----
    finalize_k<<<(86400 + 255) / 256, 256>>>(y1, y2, y3, cT1, cT2, cT3, out);
}